// round 2
// baseline (speedup 1.0000x reference)
#include <cuda_runtime.h>
#include <math.h>

#define WD 128
#define TT 64
#define XS 68          // padded row stride (floats) for time-tiles in smem
#define FO 6145        // final output length
#define TFULL 8192
#define NL 20

// ---------------- scratch (device globals; no allocations allowed) ----------
__device__ float g_x0[(size_t)8 * WD * TFULL];           // 33.5 MB
__device__ float g_x1[(size_t)8 * WD * TFULL];           // 33.5 MB
__device__ float g_acts[(size_t)8 * NL * WD * FO];       // 503 MB  [b][layer][c][t]
__device__ float g_skip[(size_t)8 * 512 * FO];           // 100 MB
__device__ float g_h[(size_t)8 * 512 * FO];              // 100 MB

// ---------------- embedding: x[b,c,t] = emb[y[b,t], c] ----------------------
__global__ void __launch_bounds__(256) embed_kernel(
    const int* __restrict__ y, const float* __restrict__ emb, float* __restrict__ x)
{
    int b = blockIdx.y;
    int t = blockIdx.x * 32 + (threadIdx.x & 31);
    int cg = threadIdx.x >> 5;                 // 0..7, 16 channels each
    int idx = y[b * TFULL + t];
    const float* er = emb + (size_t)idx * WD;
    float* xb = x + (size_t)b * WD * TFULL;
#pragma unroll
    for (int j = 0; j < 16; ++j) {
        int c = cg * 16 + j;
        xb[(size_t)c * TFULL + t] = er[c];     // coalesced over t
    }
}

// ---------------- fused per-layer kernel ------------------------------------
// Phase 1: in_act[256 x TT] = Wd_stacked^T * [x(t); x(t+d)]  (K=256 GEMM)
// Gate:    acts = tanh(lo) * sigmoid(hi); store tail slice to g_acts
// Phase 2: x_next = Wr^T * acts + br + x(t+d)                (K=128 GEMM)
__global__ void __launch_bounds__(256) layer_kernel(
    const float* __restrict__ xin, float* __restrict__ xout,
    const float* __restrict__ Wdl, const float* __restrict__ bdl,
    const float* __restrict__ Wrl, const float* __restrict__ brl,
    int d, int Lout, int layer)
{
    extern __shared__ float sm[];
    float* Xs   = sm;                      // 256 * XS  (two taps stacked)
    float* Wst  = Xs + 256 * XS;           // 16 * 256  (weight staging)
    float* Iact = Wst + 16 * 256;          // 256 * XS  (in_act, then acts in rows 0..127)

    const int tid = threadIdx.x;
    const int b = blockIdx.y;
    const int t0 = blockIdx.x * TT;
    const float* xbase = xin + (size_t)b * WD * TFULL;

    // ---- load stacked X tile: k<128 -> x[c, t0+t]; k>=128 -> x[c, t0+t+d]
    for (int idx = tid; idx < 256 * TT; idx += 256) {
        int k = idx >> 6;
        int t = idx & 63;
        int c = k & (WD - 1);
        int tg = t0 + t + ((k >= WD) ? d : 0);
        if (tg > TFULL - 1) tg = TFULL - 1;            // clamp (unused lanes only)
        Xs[k * XS + t] = xbase[(size_t)c * TFULL + tg];
    }

    float acc[8][8];
#pragma unroll
    for (int i = 0; i < 8; ++i)
#pragma unroll
        for (int j = 0; j < 8; ++j) acc[i][j] = 0.0f;

    const int orow = tid >> 3, tcol = tid & 7;
    const int ob = orow * 8, tb = tcol * 8;

    // ---- Phase 1 GEMM: K = 256, N = 256 outs, TT times
    for (int k0 = 0; k0 < 256; k0 += 16) {
        __syncthreads();
#pragma unroll
        for (int j = 0; j < 16; ++j) {
            int idx = tid + j * 256;                   // 0..4095, layout matches Wd flat
            Wst[idx] = Wdl[(size_t)k0 * 256 + idx];
        }
        __syncthreads();
#pragma unroll
        for (int kk = 0; kk < 16; ++kk) {
            const float4 wa  = *(const float4*)&Wst[kk * 256 + ob];
            const float4 wb  = *(const float4*)&Wst[kk * 256 + ob + 4];
            const float4 xa  = *(const float4*)&Xs[(k0 + kk) * XS + tb];
            const float4 xb4 = *(const float4*)&Xs[(k0 + kk) * XS + tb + 4];
            float wv[8] = {wa.x, wa.y, wa.z, wa.w, wb.x, wb.y, wb.z, wb.w};
            float xv[8] = {xa.x, xa.y, xa.z, xa.w, xb4.x, xb4.y, xb4.z, xb4.w};
#pragma unroll
            for (int oi = 0; oi < 8; ++oi)
#pragma unroll
                for (int ti = 0; ti < 8; ++ti)
                    acc[oi][ti] = fmaf(wv[oi], xv[ti], acc[oi][ti]);
        }
    }

    // ---- bias + stash in_act
#pragma unroll
    for (int oi = 0; oi < 8; ++oi) {
        float bo = bdl[ob + oi];
#pragma unroll
        for (int ti = 0; ti < 8; ++ti)
            Iact[(ob + oi) * XS + tb + ti] = acc[oi][ti] + bo;
    }
    __syncthreads();

    // ---- gate: acts = tanh * sigmoid; store tail slice to g_acts
    {
        const size_t abase = (size_t)(b * NL + layer) * WD * (size_t)FO;
        const int tail = Lout - FO;
        for (int idx = tid; idx < WD * TT; idx += 256) {
            int c = idx >> 6, t = idx & 63;
            float lo = Iact[c * XS + t];
            float hi = Iact[(c + WD) * XS + t];
            float a = tanhf(lo) * (1.0f / (1.0f + expf(-hi)));
            Iact[c * XS + t] = a;                      // reuse rows 0..127 as acts
            int tg = t0 + t;
            if (tg >= tail && tg < Lout)
                g_acts[abase + (size_t)c * FO + (tg - tail)] = a;
        }
    }
    __syncthreads();

    // ---- Phase 2 GEMM: res = Wr^T acts, K = 128, 128 outs
    float acc2[4][8];
#pragma unroll
    for (int i = 0; i < 4; ++i)
#pragma unroll
        for (int j = 0; j < 8; ++j) acc2[i][j] = 0.0f;
    const int o2 = (tid >> 3) * 4;

    for (int k0 = 0; k0 < 128; k0 += 16) {
        __syncthreads();
#pragma unroll
        for (int j = 0; j < 8; ++j) {
            int idx = tid + j * 256;                   // 0..2047
            Wst[idx] = Wrl[(size_t)k0 * 128 + idx];
        }
        __syncthreads();
#pragma unroll
        for (int kk = 0; kk < 16; ++kk) {
            const float4 w  = *(const float4*)&Wst[kk * 128 + o2];
            const float4 xa = *(const float4*)&Iact[(k0 + kk) * XS + tb];
            const float4 xc = *(const float4*)&Iact[(k0 + kk) * XS + tb + 4];
            float wv[4] = {w.x, w.y, w.z, w.w};
            float xv[8] = {xa.x, xa.y, xa.z, xa.w, xc.x, xc.y, xc.z, xc.w};
#pragma unroll
            for (int oi = 0; oi < 4; ++oi)
#pragma unroll
                for (int ti = 0; ti < 8; ++ti)
                    acc2[oi][ti] = fmaf(wv[oi], xv[ti], acc2[oi][ti]);
        }
    }

    // ---- residual add + store x_next (residual uses tap1 = x[c, t+d] already in Xs)
    float* xob = xout + (size_t)b * WD * TFULL;
#pragma unroll
    for (int oi = 0; oi < 4; ++oi) {
        int o = o2 + oi;
        float bro = brl[o];
#pragma unroll
        for (int ti = 0; ti < 8; ++ti) {
            int tg = t0 + tb + ti;
            if (tg < Lout)
                xob[(size_t)o * TFULL + tg] =
                    acc2[oi][ti] + bro + Xs[(WD + o) * XS + tb + ti];
        }
    }
}

// ---------------- generic GEMM: out[b,o,t] = sum_k X[b,k,t] * W[k,o] (+bias)(+relu)
__global__ void __launch_bounds__(256) gemm_kernel(
    const float* __restrict__ X, const float* __restrict__ W,
    const float* __restrict__ bias, int nbias, int doRelu,
    int K, int NO, float* __restrict__ out)
{
    __shared__ float Wst[16 * 256];
    __shared__ float Xst[16 * XS];

    const int tid = threadIdx.x;
    const int b = blockIdx.z;
    const int o0 = blockIdx.y * 256;
    const int t0 = blockIdx.x * TT;
    const float* Xb = X + (size_t)b * K * FO;

    float acc[8][8];
#pragma unroll
    for (int i = 0; i < 8; ++i)
#pragma unroll
        for (int j = 0; j < 8; ++j) acc[i][j] = 0.0f;

    const int orow = tid >> 3, tcol = tid & 7;
    const int ob = orow * 8, tb = tcol * 8;

    for (int k0 = 0; k0 < K; k0 += 16) {
        __syncthreads();
#pragma unroll
        for (int j = 0; j < 16; ++j) {
            int idx = tid + j * 256;
            int kk = idx >> 8, o = idx & 255;
            Wst[idx] = W[(size_t)(k0 + kk) * NO + o0 + o];
        }
#pragma unroll
        for (int j = 0; j < 4; ++j) {
            int idx = tid + j * 256;
            int kk = idx >> 6, t = idx & 63;
            int tg = t0 + t;
            if (tg > FO - 1) tg = FO - 1;              // clamp (unused lanes only)
            Xst[kk * XS + t] = Xb[(size_t)(k0 + kk) * FO + tg];
        }
        __syncthreads();
#pragma unroll
        for (int kk = 0; kk < 16; ++kk) {
            const float4 wa  = *(const float4*)&Wst[kk * 256 + ob];
            const float4 wb  = *(const float4*)&Wst[kk * 256 + ob + 4];
            const float4 xa  = *(const float4*)&Xst[kk * XS + tb];
            const float4 xb4 = *(const float4*)&Xst[kk * XS + tb + 4];
            float wv[8] = {wa.x, wa.y, wa.z, wa.w, wb.x, wb.y, wb.z, wb.w};
            float xv[8] = {xa.x, xa.y, xa.z, xa.w, xb4.x, xb4.y, xb4.z, xb4.w};
#pragma unroll
            for (int oi = 0; oi < 8; ++oi)
#pragma unroll
                for (int ti = 0; ti < 8; ++ti)
                    acc[oi][ti] = fmaf(wv[oi], xv[ti], acc[oi][ti]);
        }
    }

    float bv[8];
#pragma unroll
    for (int oi = 0; oi < 8; ++oi) bv[oi] = 0.0f;
    if (nbias > 0) {
#pragma unroll
        for (int oi = 0; oi < 8; ++oi)
            for (int i = 0; i < nbias; ++i)
                bv[oi] += bias[(size_t)i * NO + o0 + ob + oi];
    }

#pragma unroll
    for (int oi = 0; oi < 8; ++oi)
#pragma unroll
        for (int ti = 0; ti < 8; ++ti) {
            float v = acc[oi][ti] + bv[oi];
            if (doRelu) v = fmaxf(v, 0.0f);
            int tg = t0 + tb + ti;
            if (tg < FO)
                out[((size_t)b * NO + o0 + ob + oi) * FO + tg] = v;
        }
}

// ---------------- host launcher ---------------------------------------------
extern "C" void kernel_launch(void* const* d_in, const int* in_sizes, int n_in,
                              void* d_out, int out_size)
{
    const int*   y   = (const int*)d_in[0];
    const float* emb = (const float*)d_in[1];
    const float* Wd  = (const float*)d_in[2];
    const float* bd  = (const float*)d_in[3];
    const float* Wr  = (const float*)d_in[4];
    const float* br  = (const float*)d_in[5];
    const float* Ws  = (const float*)d_in[6];
    const float* bs  = (const float*)d_in[7];
    const float* p1  = (const float*)d_in[8];
    const float* p2  = (const float*)d_in[9];
    float* out = (float*)d_out;

    static const int dil[NL] = {1, 2, 4, 8, 16, 32, 64, 128, 256, 512,
                                1, 2, 4, 8, 16, 32, 64, 128, 256, 512};

    size_t smem = (size_t)(256 * XS + 16 * 256 + 256 * XS) * sizeof(float); // ~152 KB
    cudaFuncSetAttribute(layer_kernel, cudaFuncAttributeMaxDynamicSharedMemorySize, (int)smem);

    float *x0, *x1, *acts, *skip, *h;
    cudaGetSymbolAddress((void**)&x0,   g_x0);
    cudaGetSymbolAddress((void**)&x1,   g_x1);
    cudaGetSymbolAddress((void**)&acts, g_acts);
    cudaGetSymbolAddress((void**)&skip, g_skip);
    cudaGetSymbolAddress((void**)&h,    g_h);

    embed_kernel<<<dim3(TFULL / 32, 8), 256>>>(y, emb, x0);

    float* xin = x0;
    float* xout = x1;
    int Tin = TFULL;
    for (int i = 0; i < NL; ++i) {
        int d = dil[i];
        int Lout = Tin - d;
        dim3 grid((Lout + TT - 1) / TT, 8);
        layer_kernel<<<grid, 256, smem>>>(
            xin, xout,
            Wd + (size_t)i * 2 * WD * 2 * WD, bd + (size_t)i * 2 * WD,
            Wr + (size_t)i * WD * WD,         br + (size_t)i * WD,
            d, Lout, i);
        float* tmp = xin; xin = xout; xout = tmp;
        Tin = Lout;
    }

    dim3 g1((FO + TT - 1) / TT, 2, 8);  // 512 outputs -> 2 tiles
    gemm_kernel<<<g1, 256>>>(acts, Ws, bs, NL, 1, NL * WD, 512, skip);
    gemm_kernel<<<g1, 256>>>(skip, p1, nullptr, 0, 1, 512, 512, h);
    dim3 g3((FO + TT - 1) / TT, 1, 8);  // 256 outputs
    gemm_kernel<<<g3, 256>>>(h, p2, nullptr, 0, 0, 512, 256, out);
}

// round 3
// speedup vs baseline: 1.6209x; 1.6209x over previous
#include <cuda_runtime.h>
#include <math.h>

#define WD 128
#define FO 6145          // final output length
#define TFULL 8192
#define NL 20
#define NPAD 72          // smem time-stride (bank-conflict-free B frags)
#define MPAD 264         // smem out-stride  (bank-conflict-free A frags)

// ---------------- scratch (device globals; no allocations allowed) ----------
__device__ float g_x0[(size_t)8 * WD * TFULL];
__device__ float g_x1[(size_t)8 * WD * TFULL];
__device__ float g_acts[(size_t)8 * NL * WD * FO];       // [b][layer][c][t]
__device__ float g_skip[(size_t)8 * 512 * FO];
__device__ float g_h[(size_t)8 * 512 * FO];

// ---------------- helpers ---------------------------------------------------
__device__ __forceinline__ unsigned f2tf(float x) {
    unsigned u;
    asm("cvt.rna.tf32.f32 %0, %1;" : "=r"(u) : "f"(x));
    return u;
}

__device__ __forceinline__ void mma8(float* c, const unsigned a[4], const unsigned b[2]) {
    asm volatile("mma.sync.aligned.m16n8k8.row.col.f32.tf32.tf32.f32 "
                 "{%0,%1,%2,%3}, {%4,%5,%6,%7}, {%8,%9}, {%0,%1,%2,%3};\n"
                 : "+f"(c[0]), "+f"(c[1]), "+f"(c[2]), "+f"(c[3])
                 : "r"(a[0]), "r"(a[1]), "r"(a[2]), "r"(a[3]),
                   "r"(b[0]), "r"(b[1]));
}

__device__ __forceinline__ float tanh_fast(float v) {
    float t;
    asm("tanh.approx.f32 %0, %1;" : "=f"(t) : "f"(v));
    return t;
}

// ---------------- embedding: x[b,c,t] = emb[y[b,t], c] ----------------------
__global__ void __launch_bounds__(256) embed_kernel(
    const int* __restrict__ y, const float* __restrict__ emb, float* __restrict__ x)
{
    int b = blockIdx.y;
    int t = blockIdx.x * 32 + (threadIdx.x & 31);
    int cg = threadIdx.x >> 5;
    int idx = y[b * TFULL + t];
    const float* er = emb + (size_t)idx * WD;
    float* xb = x + (size_t)b * WD * TFULL;
#pragma unroll
    for (int j = 0; j < 16; ++j) {
        int c = cg * 16 + j;
        xb[(size_t)c * TFULL + t] = er[c];
    }
}

// ---------------- fused per-layer kernel (tf32 mma) -------------------------
// Phase 1: in_act[256 x 64] = Wd^T * [x(t); x(t+d)]   (M=256,N=64,K=256)
// Gate:    acts = tanh(lo)*sigmoid(hi) -> smem rows 0..127 (+ g_acts tail)
// Phase 2: x_next = Wr^T * acts + br + x(t+d)         (M=128,N=64,K=128)
__global__ void __launch_bounds__(256, 2) layer_kernel(
    const float* __restrict__ xin, float* __restrict__ xout,
    const float* __restrict__ Wdl, const float* __restrict__ bdl,
    const float* __restrict__ Wrl, const float* __restrict__ brl,
    int d, int Lout, int layer)
{
    extern __shared__ float sm[];
    float* Xs  = sm;                  // 256 x NPAD (fp32 taps; later acts/res in rows 0..127)
    float* Wst = Xs + 256 * NPAD;     // 32 x MPAD  (tf32 weight chunk)
    unsigned* Wu = (unsigned*)Wst;

    const int tid = threadIdx.x;
    const int w = tid >> 5, lane = tid & 31, g = lane >> 2, q = lane & 3;
    const int b = blockIdx.y;
    const int t0 = blockIdx.x * 64;
    const float* xb = xin + (size_t)b * WD * TFULL;

    // ---- fill stacked X tile (fp32): k<128 -> x[c,t0+t]; k>=128 -> x[c,t0+t+d]
    for (int i = tid; i < 256 * 64; i += 256) {
        int k = i >> 6, t = i & 63;
        int c = k & 127;
        int tg = t0 + t + ((k >= WD) ? d : 0);
        if (tg > TFULL - 1) tg = TFULL - 1;
        Xs[k * NPAD + t] = xb[(size_t)c * TFULL + tg];
    }

    const int m0 = (w & 3) * 64, n0 = (w >> 2) * 32;
    float acc[4][4][4];
#pragma unroll
    for (int mf = 0; mf < 4; ++mf)
#pragma unroll
        for (int nf = 0; nf < 4; ++nf)
#pragma unroll
            for (int e = 0; e < 4; ++e) acc[mf][nf][e] = 0.0f;

    // ---- Phase 1: K=256 in chunks of 32
    for (int kc = 0; kc < 256; kc += 32) {
        __syncthreads();
        for (int i = tid; i < 32 * 256; i += 256) {
            int k = i >> 8, m = i & 255;
            Wu[k * MPAD + m] = f2tf(Wdl[(size_t)(kc + k) * 256 + m]);
        }
        __syncthreads();
#pragma unroll
        for (int kk = 0; kk < 32; kk += 8) {
            unsigned a[4][4], bb[4][2];
#pragma unroll
            for (int mf = 0; mf < 4; ++mf) {
                int mm = m0 + mf * 16 + g;
                const unsigned* p0 = Wu + (kk + q) * MPAD;
                const unsigned* p1 = Wu + (kk + q + 4) * MPAD;
                a[mf][0] = p0[mm];     a[mf][1] = p0[mm + 8];
                a[mf][2] = p1[mm];     a[mf][3] = p1[mm + 8];
            }
#pragma unroll
            for (int nf = 0; nf < 4; ++nf) {
                int nn = n0 + nf * 8 + g;
                bb[nf][0] = f2tf(Xs[(kc + kk + q) * NPAD + nn]);
                bb[nf][1] = f2tf(Xs[(kc + kk + q + 4) * NPAD + nn]);
            }
#pragma unroll
            for (int mf = 0; mf < 4; ++mf)
#pragma unroll
                for (int nf = 0; nf < 4; ++nf)
                    mma8(acc[mf][nf], a[mf], bb[nf]);
        }
    }
    __syncthreads();

    // ---- gate: hi warps write sigmoid to rows 0..127, lo warps finish acts
    if (m0 >= 128) {
#pragma unroll
        for (int mf = 0; mf < 4; ++mf) {
            int r0 = m0 + mf * 16 + g;
            float b0v = bdl[r0], b1v = bdl[r0 + 8];
#pragma unroll
            for (int nf = 0; nf < 4; ++nf) {
                int c0 = n0 + nf * 8 + q * 2;
#pragma unroll
                for (int e = 0; e < 4; ++e) {
                    int row = r0 + ((e >= 2) ? 8 : 0);
                    int col = c0 + (e & 1);
                    float v = acc[mf][nf][e] + ((e >= 2) ? b1v : b0v);
                    float s = __fdividef(1.0f, 1.0f + __expf(-v));
                    Xs[(row - 128) * NPAD + col] = s;
                }
            }
        }
    }
    __syncthreads();
    if (m0 < 128) {
#pragma unroll
        for (int mf = 0; mf < 4; ++mf) {
            int r0 = m0 + mf * 16 + g;
            float b0v = bdl[r0], b1v = bdl[r0 + 8];
#pragma unroll
            for (int nf = 0; nf < 4; ++nf) {
                int c0 = n0 + nf * 8 + q * 2;
#pragma unroll
                for (int e = 0; e < 4; ++e) {
                    int row = r0 + ((e >= 2) ? 8 : 0);
                    int col = c0 + (e & 1);
                    float v = acc[mf][nf][e] + ((e >= 2) ? b1v : b0v);
                    float av = tanh_fast(v) * Xs[row * NPAD + col];
                    Xs[row * NPAD + col] = av;   // same-thread RAW then W: safe
                }
            }
        }
    }
    __syncthreads();

    // ---- store acts tail slice to g_acts (coalesced over t)
    {
        const int tail = Lout - FO;
        if (t0 + 64 > tail) {
            float* ag = g_acts + (size_t)(b * NL + layer) * WD * (size_t)FO;
            for (int i = tid; i < 128 * 64; i += 256) {
                int c = i >> 6, t = i & 63;
                int tg = t0 + t;
                if (tg >= tail && tg < Lout)
                    ag[(size_t)c * FO + (tg - tail)] = Xs[c * NPAD + t];
            }
        }
    }

    // ---- Phase 2: res GEMM (M=128,N=64,K=128)
    const int m0b = (w & 3) * 32, n0b = (w >> 2) * 32;
    float ac2[2][4][4];
#pragma unroll
    for (int mf = 0; mf < 2; ++mf)
#pragma unroll
        for (int nf = 0; nf < 4; ++nf)
#pragma unroll
            for (int e = 0; e < 4; ++e) ac2[mf][nf][e] = 0.0f;

    for (int kc = 0; kc < 128; kc += 32) {
        __syncthreads();
        for (int i = tid; i < 32 * 128; i += 256) {
            int k = i >> 7, m = i & 127;
            Wu[k * MPAD + m] = f2tf(Wrl[(size_t)(kc + k) * 128 + m]);
        }
        __syncthreads();
#pragma unroll
        for (int kk = 0; kk < 32; kk += 8) {
            unsigned a[2][4], bb[4][2];
#pragma unroll
            for (int mf = 0; mf < 2; ++mf) {
                int mm = m0b + mf * 16 + g;
                const unsigned* p0 = Wu + (kk + q) * MPAD;
                const unsigned* p1 = Wu + (kk + q + 4) * MPAD;
                a[mf][0] = p0[mm];     a[mf][1] = p0[mm + 8];
                a[mf][2] = p1[mm];     a[mf][3] = p1[mm + 8];
            }
#pragma unroll
            for (int nf = 0; nf < 4; ++nf) {
                int nn = n0b + nf * 8 + g;
                bb[nf][0] = f2tf(Xs[(kc + kk + q) * NPAD + nn]);
                bb[nf][1] = f2tf(Xs[(kc + kk + q + 4) * NPAD + nn]);
            }
#pragma unroll
            for (int mf = 0; mf < 2; ++mf)
#pragma unroll
                for (int nf = 0; nf < 4; ++nf)
                    mma8(ac2[mf][nf], a[mf], bb[nf]);
        }
    }
    __syncthreads();

    // ---- residual add (fp32 tap1 in rows 128..255), stage res into rows 0..127
#pragma unroll
    for (int mf = 0; mf < 2; ++mf) {
        int r0 = m0b + mf * 16 + g;
        float br0 = brl[r0], br1 = brl[r0 + 8];
#pragma unroll
        for (int nf = 0; nf < 4; ++nf) {
            int c0 = n0b + nf * 8 + q * 2;
#pragma unroll
            for (int e = 0; e < 4; ++e) {
                int row = r0 + ((e >= 2) ? 8 : 0);
                int col = c0 + (e & 1);
                float r = ac2[mf][nf][e] + ((e >= 2) ? br1 : br0)
                        + Xs[(128 + row) * NPAD + col];
                Xs[row * NPAD + col] = r;
            }
        }
    }
    __syncthreads();

    // ---- coalesced store x_next
    float* xo = xout + (size_t)b * WD * TFULL;
    for (int i = tid; i < 128 * 64; i += 256) {
        int c = i >> 6, t = i & 63;
        int tg = t0 + t;
        if (tg < Lout)
            xo[(size_t)c * TFULL + tg] = Xs[c * NPAD + t];
    }
}

// ---------------- generic GEMM (tf32 mma): out[b,o,t]=sum_k X[b,k,t]*W[k,o] --
__global__ void __launch_bounds__(256) gemm_mma(
    const float* __restrict__ X, const float* __restrict__ W,
    const float* __restrict__ bias, int nbias, int doRelu,
    int K, int NO, float* __restrict__ out)
{
    __shared__ float Wst[32 * MPAD];
    __shared__ float Xst[32 * NPAD];
    unsigned* Wu = (unsigned*)Wst;

    const int tid = threadIdx.x;
    const int w = tid >> 5, lane = tid & 31, g = lane >> 2, q = lane & 3;
    const int b = blockIdx.z;
    const int o0 = blockIdx.y * 256;
    const int t0 = blockIdx.x * 64;
    const float* Xb = X + (size_t)b * K * FO;

    const int m0 = (w & 3) * 64, n0 = (w >> 2) * 32;
    float acc[4][4][4];
#pragma unroll
    for (int mf = 0; mf < 4; ++mf)
#pragma unroll
        for (int nf = 0; nf < 4; ++nf)
#pragma unroll
            for (int e = 0; e < 4; ++e) acc[mf][nf][e] = 0.0f;

    for (int kc = 0; kc < K; kc += 32) {
        __syncthreads();
        for (int i = tid; i < 32 * 256; i += 256) {
            int k = i >> 8, m = i & 255;
            Wu[k * MPAD + m] = f2tf(W[(size_t)(kc + k) * NO + o0 + m]);
        }
        for (int i = tid; i < 32 * 64; i += 256) {
            int k = i >> 6, t = i & 63;
            int tg = t0 + t;
            if (tg > FO - 1) tg = FO - 1;
            Xst[k * NPAD + t] = Xb[(size_t)(kc + k) * FO + tg];
        }
        __syncthreads();
#pragma unroll
        for (int kk = 0; kk < 32; kk += 8) {
            unsigned a[4][4], bb[4][2];
#pragma unroll
            for (int mf = 0; mf < 4; ++mf) {
                int mm = m0 + mf * 16 + g;
                const unsigned* p0 = Wu + (kk + q) * MPAD;
                const unsigned* p1 = Wu + (kk + q + 4) * MPAD;
                a[mf][0] = p0[mm];     a[mf][1] = p0[mm + 8];
                a[mf][2] = p1[mm];     a[mf][3] = p1[mm + 8];
            }
#pragma unroll
            for (int nf = 0; nf < 4; ++nf) {
                int nn = n0 + nf * 8 + g;
                bb[nf][0] = f2tf(Xst[(kk + q) * NPAD + nn]);
                bb[nf][1] = f2tf(Xst[(kk + q + 4) * NPAD + nn]);
            }
#pragma unroll
            for (int mf = 0; mf < 4; ++mf)
#pragma unroll
                for (int nf = 0; nf < 4; ++nf)
                    mma8(acc[mf][nf], a[mf], bb[nf]);
        }
    }

    // epilogue: bias sum + relu + guarded stores
#pragma unroll
    for (int mf = 0; mf < 4; ++mf) {
        int r0 = o0 + m0 + mf * 16 + g;
        float bs0 = 0.0f, bs1 = 0.0f;
        for (int i = 0; i < nbias; ++i) {
            bs0 += bias[(size_t)i * NO + r0];
            bs1 += bias[(size_t)i * NO + r0 + 8];
        }
#pragma unroll
        for (int nf = 0; nf < 4; ++nf) {
            int c0 = t0 + n0 + nf * 8 + q * 2;
#pragma unroll
            for (int e = 0; e < 4; ++e) {
                int row = r0 + ((e >= 2) ? 8 : 0);
                int t = c0 + (e & 1);
                float v = acc[mf][nf][e] + ((e >= 2) ? bs1 : bs0);
                if (doRelu) v = fmaxf(v, 0.0f);
                if (t < FO)
                    out[((size_t)b * NO + row) * FO + t] = v;
            }
        }
    }
}

// ---------------- host launcher ---------------------------------------------
extern "C" void kernel_launch(void* const* d_in, const int* in_sizes, int n_in,
                              void* d_out, int out_size)
{
    const int*   y   = (const int*)d_in[0];
    const float* emb = (const float*)d_in[1];
    const float* Wd  = (const float*)d_in[2];
    const float* bd  = (const float*)d_in[3];
    const float* Wr  = (const float*)d_in[4];
    const float* br  = (const float*)d_in[5];
    const float* Ws  = (const float*)d_in[6];
    const float* bs  = (const float*)d_in[7];
    const float* p1  = (const float*)d_in[8];
    const float* p2  = (const float*)d_in[9];
    float* out = (float*)d_out;

    static const int dil[NL] = {1, 2, 4, 8, 16, 32, 64, 128, 256, 512,
                                1, 2, 4, 8, 16, 32, 64, 128, 256, 512};

    size_t smem = (size_t)(256 * NPAD + 32 * MPAD) * sizeof(float);   // 107,520 B
    cudaFuncSetAttribute(layer_kernel, cudaFuncAttributeMaxDynamicSharedMemorySize, (int)smem);

    float *x0, *x1, *acts, *skip, *h;
    cudaGetSymbolAddress((void**)&x0,   g_x0);
    cudaGetSymbolAddress((void**)&x1,   g_x1);
    cudaGetSymbolAddress((void**)&acts, g_acts);
    cudaGetSymbolAddress((void**)&skip, g_skip);
    cudaGetSymbolAddress((void**)&h,    g_h);

    embed_kernel<<<dim3(TFULL / 32, 8), 256>>>(y, emb, x0);

    float* xin = x0;
    float* xout = x1;
    int Tin = TFULL;
    for (int i = 0; i < NL; ++i) {
        int d = dil[i];
        int Lout = Tin - d;
        dim3 grid((Lout + 63) / 64, 8);
        layer_kernel<<<grid, 256, smem>>>(
            xin, xout,
            Wd + (size_t)i * 2 * WD * 2 * WD, bd + (size_t)i * 2 * WD,
            Wr + (size_t)i * WD * WD,         br + (size_t)i * WD,
            d, Lout, i);
        float* tmp = xin; xin = xout; xout = tmp;
        Tin = Lout;
    }

    dim3 g1((FO + 63) / 64, 2, 8);   // 512 outputs -> 2 o-tiles
    gemm_mma<<<g1, 256>>>(acts, Ws, bs, NL, 1, NL * WD, 512, skip);
    gemm_mma<<<g1, 256>>>(skip, p1, nullptr, 0, 1, 512, 512, h);
    dim3 g3((FO + 63) / 64, 1, 8);   // 256 outputs
    gemm_mma<<<g3, 256>>>(h, p2, nullptr, 0, 0, 512, 256, out);
}

// round 4
// speedup vs baseline: 2.3556x; 1.4533x over previous
#include <cuda_runtime.h>
#include <math.h>

#define WD 128
#define FO 6145
#define FOP 6208          // padded time stride for scratch (mult of 64)
#define TFULL 8192
#define NL 20

// swizzle functions (XOR on float4-chunk index; keep LDS.128 conflict-free)
#define FB(k) ((((k)&1)<<2) | (((k)>>1)&1))   // 0,4,1,5  (64-wide rows)
#define F2(k) ((((k)&1)<<2) | ((k)&2))        // 0,4,2,6  (32-wide A blocks)

// ---------------- scratch (device globals; no allocations allowed) ----------
__device__ __align__(256) float g_x0[(size_t)8 * WD * TFULL + 2048];
__device__ __align__(256) float g_x1[(size_t)8 * WD * TFULL + 2048];
__device__ __align__(256) float g_acts[(size_t)8 * NL * WD * FOP];
__device__ __align__(256) float g_skip[(size_t)8 * 512 * FOP];
__device__ __align__(256) float g_h[(size_t)8 * 512 * FOP];
__device__ __align__(256) float g_imgWd[(size_t)NL * 256 * 256];
__device__ __align__(256) float g_imgWr[(size_t)NL * 128 * 128];
__device__ __align__(256) float g_imgWs[(size_t)2560 * 512];
__device__ __align__(256) float g_imgP1[(size_t)512 * 512];
__device__ __align__(256) float g_imgP2[(size_t)512 * 256];

// ---------------- helpers ---------------------------------------------------
__device__ __forceinline__ unsigned f2tf(float x) {
    unsigned u;
    asm("cvt.rna.tf32.f32 %0, %1;" : "=r"(u) : "f"(x));
    return u;
}
__device__ __forceinline__ void mma8(float* c, const unsigned a[4], const unsigned b[2]) {
    asm volatile("mma.sync.aligned.m16n8k8.row.col.f32.tf32.tf32.f32 "
                 "{%0,%1,%2,%3}, {%4,%5,%6,%7}, {%8,%9}, {%0,%1,%2,%3};\n"
                 : "+f"(c[0]), "+f"(c[1]), "+f"(c[2]), "+f"(c[3])
                 : "r"(a[0]), "r"(a[1]), "r"(a[2]), "r"(a[3]),
                   "r"(b[0]), "r"(b[1]));
}
__device__ __forceinline__ float tanh_fast(float v) {
    float t;
    asm("tanh.approx.f32 %0, %1;" : "=f"(t) : "f"(v));
    return t;
}
// swizzled float offset of time-index t within a 64-float row, row mod-4 = k
__device__ __forceinline__ int swzB(int t, int fk) {
    int p = ((t & 7) << 3) | (t >> 3);
    return ((((p >> 2) ^ fk)) << 2) | (p & 3);
}
// store 4 consecutive t values (t4 aligned to 4) as tf32 into swizzled row
__device__ __forceinline__ void store4(float* row, int t4, int fk, float4 v) {
    int p0 = ((t4 & 7) << 3) | (t4 >> 3);
    int c0 = p0 >> 2, lo = p0 & 3;
    row[((((c0 + 0) ^ fk)) << 2) | lo] = __uint_as_float(f2tf(v.x));
    row[((((c0 + 2) ^ fk)) << 2) | lo] = __uint_as_float(f2tf(v.y));
    row[((((c0 + 4) ^ fk)) << 2) | lo] = __uint_as_float(f2tf(v.z));
    row[((((c0 + 6) ^ fk)) << 2) | lo] = __uint_as_float(f2tf(v.w));
}

// ---------------- weight image prep (one-time per launch) -------------------
// 64-block A layout: img[((ot*(K/32)+ch)*32 + kk)*256 + pos], tf32 bits
__global__ void __launch_bounds__(256) prep64(
    const float* __restrict__ W, int K, int NO, float* __restrict__ img)
{
    int idx = blockIdx.x * 256 + threadIdx.x;
    if (idx >= K * NO) return;
    int k = idx / NO, o = idx - k * NO;
    int ot = o >> 8, m = o & 255;
    int ch = k >> 5, kk = k & 31;
    int p = ((m & 7) << 3) | ((m >> 3) & 7);
    int pos = (m & ~63) + ((((p >> 2) ^ FB(kk & 3))) << 2) + (p & 3);
    img[((size_t)(ot * (K >> 5) + ch) * 32 + kk) * 256 + pos] =
        __uint_as_float(f2tf(W[idx]));
}
// 32-block A layout for Wr (NO = 128)
__global__ void __launch_bounds__(256) prep32(
    const float* __restrict__ W, int K, float* __restrict__ img)
{
    int idx = blockIdx.x * 256 + threadIdx.x;
    if (idx >= K * 128) return;
    int k = idx >> 7, m = idx & 127;
    int ch = k >> 5, kk = k & 31;
    int p = ((m & 7) << 2) | ((m >> 3) & 3);
    int pos = (m & ~31) + ((((p >> 2) ^ F2(kk & 3))) << 2) + (p & 3);
    img[((size_t)ch * 32 + kk) * 128 + pos] = __uint_as_float(f2tf(W[idx]));
}

// ---------------- embedding -------------------------------------------------
__global__ void __launch_bounds__(256) embed_kernel(
    const int* __restrict__ y, const float* __restrict__ emb, float* __restrict__ x)
{
    int b = blockIdx.y;
    int t = blockIdx.x * 32 + (threadIdx.x & 31);
    int cg = threadIdx.x >> 5;
    int idx = y[b * TFULL + t];
    const float* er = emb + (size_t)idx * WD;
    float* xb = x + (size_t)b * WD * TFULL;
#pragma unroll
    for (int j = 0; j < 16; ++j) {
        int c = cg * 16 + j;
        xb[(size_t)c * TFULL + t] = er[c];
    }
}

// ---------------- fused per-layer kernel ------------------------------------
__global__ void __launch_bounds__(256, 2) layer_kernel(
    const float* __restrict__ xin, float* __restrict__ xout,
    const float* __restrict__ imgWd, const float* __restrict__ bdl,
    const float* __restrict__ imgWr, const float* __restrict__ brl,
    int d, int Lout, int layer)
{
    extern __shared__ float sm[];
    float* Xs  = sm;                 // 256 x 64 (swizzled tf32; rows 0..127 later = acts)
    float* Wst = sm + 256 * 64;      // 32 x 256
    const unsigned* WuC = (const unsigned*)Wst;

    const int tid = threadIdx.x;
    const int w = tid >> 5, lane = tid & 31, g = lane >> 2, q = lane & 3;
    const int b = blockIdx.y;
    const int t0 = blockIdx.x * 64;
    const float* xb = xin + (size_t)b * WD * TFULL;

    // ---- tile load (tf32 into swizzled layout)
    for (int i = tid; i < 128 * 16; i += 256) {        // tap0 rows 0..127
        int k = i >> 4, t4 = (i & 15) << 2;
        float4 v = *(const float4*)(xb + (size_t)k * TFULL + t0 + t4);
        store4(Xs + k * 64, t4, FB(k & 3), v);
    }
    if ((d & 3) == 0) {                                 // tap1 rows 128..255
        for (int i = tid; i < 128 * 16; i += 256) {
            int k = i >> 4, t4 = (i & 15) << 2;
            float4 v = *(const float4*)(xb + (size_t)k * TFULL + t0 + t4 + d);
            store4(Xs + (128 + k) * 64, t4, FB(k & 3), v);
        }
    } else {
        for (int i = tid; i < 128 * 64; i += 256) {
            int k = i >> 6, t = i & 63;
            float vv = xb[(size_t)k * TFULL + t0 + t + d];
            Xs[(128 + k) * 64 + swzB(t, FB(k & 3))] = __uint_as_float(f2tf(vv));
        }
    }

    const int m0 = (w & 3) * 64, n0 = (w >> 2) * 32;
    const int fq = FB(q);
    const int offA0 = m0 + (((2 * g)     ^ fq) << 2);
    const int offA1 = m0 + (((2 * g + 1) ^ fq) << 2);
    const int offB  = (((g * 2 + (n0 >> 5)) ^ fq) << 2);

    float acc[4][4][4];
#pragma unroll
    for (int mf = 0; mf < 4; ++mf)
#pragma unroll
        for (int nf = 0; nf < 4; ++nf)
#pragma unroll
            for (int e = 0; e < 4; ++e) acc[mf][nf][e] = 0.0f;

    // ---- Phase 1: K = 256
    for (int kc = 0; kc < 256; kc += 32) {
        __syncthreads();
        {
            const float4* src = (const float4*)(imgWd + (size_t)(layer * 8 + (kc >> 5)) * 8192);
            float4* dst = (float4*)Wst;
            for (int i = tid; i < 2048; i += 256) dst[i] = src[i];
        }
        __syncthreads();
#pragma unroll
        for (int kk = 0; kk < 32; kk += 8) {
            const unsigned* W1 = WuC + (kk + q) * 256;
            const unsigned* W2 = W1 + 4 * 256;
            uint4 a0 = *(const uint4*)(W1 + offA0);
            uint4 a1 = *(const uint4*)(W1 + offA1);
            uint4 a2 = *(const uint4*)(W2 + offA0);
            uint4 a3 = *(const uint4*)(W2 + offA1);
            const unsigned* B1 = (const unsigned*)Xs + (kc + kk + q) * 64;
            uint4 b0 = *(const uint4*)(B1 + offB);
            uint4 b1 = *(const uint4*)(B1 + 4 * 64 + offB);
            unsigned A[4][4] = {{a0.x, a0.y, a2.x, a2.y}, {a0.z, a0.w, a2.z, a2.w},
                                {a1.x, a1.y, a3.x, a3.y}, {a1.z, a1.w, a3.z, a3.w}};
            unsigned Bf[4][2] = {{b0.x, b1.x}, {b0.y, b1.y}, {b0.z, b1.z}, {b0.w, b1.w}};
#pragma unroll
            for (int mf = 0; mf < 4; ++mf)
#pragma unroll
                for (int nf = 0; nf < 4; ++nf)
                    mma8(acc[mf][nf], A[mf], Bf[nf]);
        }
    }
    __syncthreads();

    // ---- gate: hi warps write sigmoid, lo warps finish acts (tf32)
    if (m0 >= 128) {
#pragma unroll
        for (int mf = 0; mf < 4; ++mf) {
            int r0 = m0 + mf * 16 + g;
            float b0v = bdl[r0], b1v = bdl[r0 + 8];
#pragma unroll
            for (int nf = 0; nf < 4; ++nf) {
                int c0 = n0 + nf * 8 + q * 2;
#pragma unroll
                for (int e = 0; e < 4; ++e) {
                    int row = r0 + ((e >= 2) ? 8 : 0);
                    int col = c0 + (e & 1);
                    float v = acc[mf][nf][e] + ((e >= 2) ? b1v : b0v);
                    float s = __fdividef(1.0f, 1.0f + __expf(-v));
                    Xs[(row - 128) * 64 + swzB(col, FB(row & 3))] = s;
                }
            }
        }
    }
    __syncthreads();
    if (m0 < 128) {
#pragma unroll
        for (int mf = 0; mf < 4; ++mf) {
            int r0 = m0 + mf * 16 + g;
            float b0v = bdl[r0], b1v = bdl[r0 + 8];
#pragma unroll
            for (int nf = 0; nf < 4; ++nf) {
                int c0 = n0 + nf * 8 + q * 2;
#pragma unroll
                for (int e = 0; e < 4; ++e) {
                    int row = r0 + ((e >= 2) ? 8 : 0);
                    int col = c0 + (e & 1);
                    float v = acc[mf][nf][e] + ((e >= 2) ? b1v : b0v);
                    int off = row * 64 + swzB(col, FB(row & 3));
                    float av = tanh_fast(v) * Xs[off];
                    Xs[off] = __uint_as_float(f2tf(av));
                }
            }
        }
    }
    __syncthreads();

    // ---- store acts tail slice to g_acts
    {
        const int tail = Lout - FO;
        if (t0 + 64 > tail) {
            float* ag = g_acts + (size_t)(b * NL + layer) * WD * FOP;
            for (int i = tid; i < 128 * 64; i += 256) {
                int c = i >> 6, t = i & 63, tg = t0 + t;
                if (tg >= tail && tg < Lout)
                    ag[(size_t)c * FOP + (tg - tail)] = Xs[c * 64 + swzB(t, FB(c & 3))];
            }
        }
    }

    // ---- Phase 2: res GEMM (M=128, N=64, K=128)
    const int m0b = (w & 3) * 32;
    const int offA2 = m0b + ((g ^ F2(q)) << 2);
    float ac2[2][4][4];
#pragma unroll
    for (int mf = 0; mf < 2; ++mf)
#pragma unroll
        for (int nf = 0; nf < 4; ++nf)
#pragma unroll
            for (int e = 0; e < 4; ++e) ac2[mf][nf][e] = 0.0f;

    for (int kc = 0; kc < 128; kc += 32) {
        __syncthreads();
        {
            const float4* src = (const float4*)(imgWr + (size_t)(layer * 4 + (kc >> 5)) * 4096);
            float4* dst = (float4*)Wst;
            for (int i = tid; i < 1024; i += 256) dst[i] = src[i];
        }
        __syncthreads();
#pragma unroll
        for (int kk = 0; kk < 32; kk += 8) {
            const unsigned* W1 = WuC + (kk + q) * 128;
            const unsigned* W2 = W1 + 4 * 128;
            uint4 a0 = *(const uint4*)(W1 + offA2);
            uint4 a2 = *(const uint4*)(W2 + offA2);
            const unsigned* B1 = (const unsigned*)Xs + (kc + kk + q) * 64;
            uint4 b0 = *(const uint4*)(B1 + offB);
            uint4 b1 = *(const uint4*)(B1 + 4 * 64 + offB);
            unsigned A2r[2][4] = {{a0.x, a0.y, a2.x, a2.y}, {a0.z, a0.w, a2.z, a2.w}};
            unsigned Bf[4][2] = {{b0.x, b1.x}, {b0.y, b1.y}, {b0.z, b1.z}, {b0.w, b1.w}};
#pragma unroll
            for (int mf = 0; mf < 2; ++mf)
#pragma unroll
                for (int nf = 0; nf < 4; ++nf)
                    mma8(ac2[mf][nf], A2r[mf], Bf[nf]);
        }
    }

    // ---- stage res (+bias) into rows 128..255 (linear), then residual+store
    float* Rs = Xs + 128 * 64;
#pragma unroll
    for (int mf = 0; mf < 2; ++mf) {
        int r0 = m0b + mf * 16 + g;
        float br0 = brl[r0], br1 = brl[r0 + 8];
#pragma unroll
        for (int nf = 0; nf < 4; ++nf) {
            int c0 = n0 + nf * 8 + q * 2;
#pragma unroll
            for (int e = 0; e < 4; ++e) {
                int row = r0 + ((e >= 2) ? 8 : 0);
                int col = c0 + (e & 1);
                Rs[row * 64 + col] = ac2[mf][nf][e] + ((e >= 2) ? br1 : br0);
            }
        }
    }
    __syncthreads();

    float* xo = xout + (size_t)b * WD * TFULL;
    for (int i = tid; i < 128 * 64; i += 256) {
        int c = i >> 6, t = i & 63, tg = t0 + t;
        if (tg < Lout)
            xo[(size_t)c * TFULL + tg] = Rs[c * 64 + t] + xb[(size_t)c * TFULL + tg + d];
    }
}

// ---------------- generic GEMM (pre-imaged weights) -------------------------
__global__ void __launch_bounds__(256, 2) gemm_mma(
    const float* __restrict__ X, const float* __restrict__ imgW,
    const float* __restrict__ bias, int nbias, int doRelu,
    int K, int NO, float* __restrict__ out, int ostride, int olimit)
{
    __shared__ float Wst[32 * 256];
    __shared__ float Xst[32 * 64];
    const unsigned* WuC = (const unsigned*)Wst;

    const int tid = threadIdx.x;
    const int w = tid >> 5, lane = tid & 31, g = lane >> 2, q = lane & 3;
    const int b = blockIdx.z, ot = blockIdx.y;
    const int t0 = blockIdx.x * 64;
    const float* Xb = X + (size_t)b * K * FOP;
    const int nch = K >> 5;

    const int m0 = (w & 3) * 64, n0 = (w >> 2) * 32;
    const int fq = FB(q);
    const int offA0 = m0 + (((2 * g)     ^ fq) << 2);
    const int offA1 = m0 + (((2 * g + 1) ^ fq) << 2);
    const int offB  = (((g * 2 + (n0 >> 5)) ^ fq) << 2);

    float acc[4][4][4];
#pragma unroll
    for (int mf = 0; mf < 4; ++mf)
#pragma unroll
        for (int nf = 0; nf < 4; ++nf)
#pragma unroll
            for (int e = 0; e < 4; ++e) acc[mf][nf][e] = 0.0f;

    for (int kc = 0; kc < K; kc += 32) {
        __syncthreads();
        {
            const float4* src = (const float4*)(imgW + (size_t)(ot * nch + (kc >> 5)) * 8192);
            float4* dst = (float4*)Wst;
            for (int i = tid; i < 2048; i += 256) dst[i] = src[i];
        }
        for (int i = tid; i < 32 * 16; i += 256) {
            int k = i >> 4, t4 = (i & 15) << 2;
            float4 v = *(const float4*)(Xb + (size_t)(kc + k) * FOP + t0 + t4);
            store4(Xst + k * 64, t4, FB(k & 3), v);
        }
        __syncthreads();
#pragma unroll
        for (int kk = 0; kk < 32; kk += 8) {
            const unsigned* W1 = WuC + (kk + q) * 256;
            const unsigned* W2 = W1 + 4 * 256;
            uint4 a0 = *(const uint4*)(W1 + offA0);
            uint4 a1 = *(const uint4*)(W1 + offA1);
            uint4 a2 = *(const uint4*)(W2 + offA0);
            uint4 a3 = *(const uint4*)(W2 + offA1);
            const unsigned* B1 = (const unsigned*)Xst + (kk + q) * 64;
            uint4 b0 = *(const uint4*)(B1 + offB);
            uint4 b1 = *(const uint4*)(B1 + 4 * 64 + offB);
            unsigned A[4][4] = {{a0.x, a0.y, a2.x, a2.y}, {a0.z, a0.w, a2.z, a2.w},
                                {a1.x, a1.y, a3.x, a3.y}, {a1.z, a1.w, a3.z, a3.w}};
            unsigned Bf[4][2] = {{b0.x, b1.x}, {b0.y, b1.y}, {b0.z, b1.z}, {b0.w, b1.w}};
#pragma unroll
            for (int mf = 0; mf < 4; ++mf)
#pragma unroll
                for (int nf = 0; nf < 4; ++nf)
                    mma8(acc[mf][nf], A[mf], Bf[nf]);
        }
    }

    // epilogue
#pragma unroll
    for (int mf = 0; mf < 4; ++mf) {
        int r0 = ot * 256 + m0 + mf * 16 + g;
        float bs0 = 0.0f, bs1 = 0.0f;
        for (int i = 0; i < nbias; ++i) {
            bs0 += bias[(size_t)i * NO + r0];
            bs1 += bias[(size_t)i * NO + r0 + 8];
        }
#pragma unroll
        for (int nf = 0; nf < 4; ++nf) {
            int c0 = t0 + n0 + nf * 8 + q * 2;
#pragma unroll
            for (int e = 0; e < 4; ++e) {
                int row = r0 + ((e >= 2) ? 8 : 0);
                int t = c0 + (e & 1);
                float v = acc[mf][nf][e] + ((e >= 2) ? bs1 : bs0);
                if (doRelu) v = fmaxf(v, 0.0f);
                if (t < olimit)
                    out[((size_t)b * NO + row) * ostride + t] = v;
            }
        }
    }
}

// ---------------- host launcher ---------------------------------------------
extern "C" void kernel_launch(void* const* d_in, const int* in_sizes, int n_in,
                              void* d_out, int out_size)
{
    const int*   y   = (const int*)d_in[0];
    const float* emb = (const float*)d_in[1];
    const float* Wd  = (const float*)d_in[2];
    const float* bd  = (const float*)d_in[3];
    const float* Wr  = (const float*)d_in[4];
    const float* br  = (const float*)d_in[5];
    const float* Ws  = (const float*)d_in[6];
    const float* bs  = (const float*)d_in[7];
    const float* p1  = (const float*)d_in[8];
    const float* p2  = (const float*)d_in[9];
    float* out = (float*)d_out;

    static const int dil[NL] = {1, 2, 4, 8, 16, 32, 64, 128, 256, 512,
                                1, 2, 4, 8, 16, 32, 64, 128, 256, 512};

    size_t smem = (size_t)(256 * 64 + 32 * 256) * sizeof(float);   // 98,304 B
    cudaFuncSetAttribute(layer_kernel, cudaFuncAttributeMaxDynamicSharedMemorySize, (int)smem);

    float *x0, *x1, *acts, *skip, *h;
    float *iWd, *iWr, *iWs, *iP1, *iP2;
    cudaGetSymbolAddress((void**)&x0,   g_x0);
    cudaGetSymbolAddress((void**)&x1,   g_x1);
    cudaGetSymbolAddress((void**)&acts, g_acts);
    cudaGetSymbolAddress((void**)&skip, g_skip);
    cudaGetSymbolAddress((void**)&h,    g_h);
    cudaGetSymbolAddress((void**)&iWd,  g_imgWd);
    cudaGetSymbolAddress((void**)&iWr,  g_imgWr);
    cudaGetSymbolAddress((void**)&iWs,  g_imgWs);
    cudaGetSymbolAddress((void**)&iP1,  g_imgP1);
    cudaGetSymbolAddress((void**)&iP2,  g_imgP2);

    // one-time weight images (tf32 + fragment permutation + swizzle)
    prep64<<<5120, 256>>>(Wd, 5120, 256, iWd);
    prep32<<<1280, 256>>>(Wr, 2560, iWr);
    prep64<<<5120, 256>>>(Ws, 2560, 512, iWs);
    prep64<<<1024, 256>>>(p1, 512, 512, iP1);
    prep64<<<512,  256>>>(p2, 512, 256, iP2);

    embed_kernel<<<dim3(TFULL / 32, 8), 256>>>(y, emb, x0);

    float* xin = x0;
    float* xout = x1;
    int Tin = TFULL;
    for (int i = 0; i < NL; ++i) {
        int d = dil[i];
        int Lout = Tin - d;
        dim3 grid((Lout + 63) / 64, 8);
        layer_kernel<<<grid, 256, smem>>>(
            xin, xout,
            iWd, bd + (size_t)i * 2 * WD,
            iWr, br + (size_t)i * WD,
            d, Lout, i);
        float* tmp = xin; xin = xout; xout = tmp;
        Tin = Lout;
    }

    dim3 g1((FOP + 63) / 64, 2, 8);
    gemm_mma<<<g1, 256>>>(acts, iWs, bs, NL, 1, NL * WD, 512, skip, FOP, FOP);
    gemm_mma<<<g1, 256>>>(skip, iP1, nullptr, 0, 1, 512, 512, h, FOP, FOP);
    dim3 g3((FOP + 63) / 64, 1, 8);
    gemm_mma<<<g3, 256>>>(h, iP2, nullptr, 0, 0, 512, 256, out, FO, FO);
}

// round 5
// speedup vs baseline: 2.6147x; 1.1100x over previous
#include <cuda_runtime.h>
#include <math.h>

#define WD 128
#define FO 6145
#define FOP 6208          // padded time stride for scratch (mult of 64)
#define TFULL 8192
#define NL 20

// swizzle functions (XOR on float4-chunk index; keep LDS.128 conflict-free)
#define FB(k) ((((k)&1)<<2) | (((k)>>1)&1))   // 0,4,1,5  (64-wide rows)
#define F2(k) ((((k)&1)<<2) | ((k)&2))        // 0,4,2,6  (32-wide A blocks)

// ---------------- scratch (device globals; no allocations allowed) ----------
__device__ __align__(256) float g_x0[(size_t)8 * WD * TFULL + 2048];
__device__ __align__(256) float g_x1[(size_t)8 * WD * TFULL + 2048];
__device__ __align__(256) float g_acts[(size_t)8 * NL * WD * FOP + 512];
__device__ __align__(256) float g_skip[(size_t)8 * 512 * FOP + 512];
__device__ __align__(256) float g_h[(size_t)8 * 512 * FOP + 512];
__device__ __align__(256) float g_imgWd[(size_t)NL * 256 * 256];
__device__ __align__(256) float g_imgWr[(size_t)NL * 128 * 128];
__device__ __align__(256) float g_imgWs[(size_t)2560 * 512];
__device__ __align__(256) float g_imgP1[(size_t)512 * 512];
__device__ __align__(256) float g_imgP2[(size_t)512 * 256];

// ---------------- helpers ---------------------------------------------------
__device__ __forceinline__ unsigned f2tf(float x) {
    unsigned u;
    asm("cvt.rna.tf32.f32 %0, %1;" : "=r"(u) : "f"(x));
    return u;
}
__device__ __forceinline__ void mma8(float* c, const unsigned a[4], const unsigned b[2]) {
    asm volatile("mma.sync.aligned.m16n8k8.row.col.f32.tf32.tf32.f32 "
                 "{%0,%1,%2,%3}, {%4,%5,%6,%7}, {%8,%9}, {%0,%1,%2,%3};\n"
                 : "+f"(c[0]), "+f"(c[1]), "+f"(c[2]), "+f"(c[3])
                 : "r"(a[0]), "r"(a[1]), "r"(a[2]), "r"(a[3]),
                   "r"(b[0]), "r"(b[1]));
}
__device__ __forceinline__ float tanh_fast(float v) {
    float t;
    asm("tanh.approx.f32 %0, %1;" : "=f"(t) : "f"(v));
    return t;
}
__device__ __forceinline__ void cp16(float4* dst_smem, const float4* src) {
    unsigned a = (unsigned)__cvta_generic_to_shared(dst_smem);
    asm volatile("cp.async.cg.shared.global [%0], [%1], 16;" :: "r"(a), "l"(src));
}
#define CP_COMMIT asm volatile("cp.async.commit_group;")
#define CP_WAIT0  asm volatile("cp.async.wait_group 0;")

// swizzled float offset of time-index t within a 64-float row, row mod-4 = k
__device__ __forceinline__ int swzB(int t, int fk) {
    int p = ((t & 7) << 3) | (t >> 3);
    return ((((p >> 2) ^ fk)) << 2) | (p & 3);
}
// swizzled offset within a 128-float row
__device__ __forceinline__ int swzB128(int t, int fk) {
    return ((t >> 6) << 6) + swzB(t & 63, fk);
}
// store 4 consecutive t values (t4 aligned to 4, t4 in [0,64)) into swizzled 64-row
__device__ __forceinline__ void store4(float* row, int t4, int fk, float4 v) {
    int p0 = ((t4 & 7) << 3) | (t4 >> 3);
    int c0 = p0 >> 2, lo = p0 & 3;
    row[((((c0 + 0) ^ fk)) << 2) | lo] = __uint_as_float(f2tf(v.x));
    row[((((c0 + 2) ^ fk)) << 2) | lo] = __uint_as_float(f2tf(v.y));
    row[((((c0 + 4) ^ fk)) << 2) | lo] = __uint_as_float(f2tf(v.z));
    row[((((c0 + 6) ^ fk)) << 2) | lo] = __uint_as_float(f2tf(v.w));
}
// same for 128-wide rows
__device__ __forceinline__ void store4_128(float* row, int t4, int fk, float4 v) {
    store4(row + ((t4 >> 6) << 6), t4 & 63, fk, v);
}

// ---------------- weight image prep (one-time per launch) -------------------
__global__ void __launch_bounds__(256) prep64(
    const float* __restrict__ W, int K, int NO, float* __restrict__ img)
{
    int idx = blockIdx.x * 256 + threadIdx.x;
    if (idx >= K * NO) return;
    int k = idx / NO, o = idx - k * NO;
    int ot = o >> 8, m = o & 255;
    int ch = k >> 5, kk = k & 31;
    int p = ((m & 7) << 3) | ((m >> 3) & 7);
    int pos = (m & ~63) + ((((p >> 2) ^ FB(kk & 3))) << 2) + (p & 3);
    img[((size_t)(ot * (K >> 5) + ch) * 32 + kk) * 256 + pos] =
        __uint_as_float(f2tf(W[idx]));
}
__global__ void __launch_bounds__(256) prep32(
    const float* __restrict__ W, int K, float* __restrict__ img)
{
    int idx = blockIdx.x * 256 + threadIdx.x;
    if (idx >= K * 128) return;
    int k = idx >> 7, m = idx & 127;
    int ch = k >> 5, kk = k & 31;
    int p = ((m & 7) << 2) | ((m >> 3) & 3);
    int pos = (m & ~31) + ((((p >> 2) ^ F2(kk & 3))) << 2) + (p & 3);
    img[((size_t)ch * 32 + kk) * 128 + pos] = __uint_as_float(f2tf(W[idx]));
}

// ---------------- embedding -------------------------------------------------
__global__ void __launch_bounds__(256) embed_kernel(
    const int* __restrict__ y, const float* __restrict__ emb, float* __restrict__ x)
{
    int b = blockIdx.y;
    int t = blockIdx.x * 32 + (threadIdx.x & 31);
    int cg = threadIdx.x >> 5;
    int idx = y[b * TFULL + t];
    const float* er = emb + (size_t)idx * WD;
    float* xb = x + (size_t)b * WD * TFULL;
#pragma unroll
    for (int j = 0; j < 16; ++j) {
        int c = cg * 16 + j;
        xb[(size_t)c * TFULL + t] = er[c];
    }
}

// ---------------- fused per-layer kernel (512 thr, 128-t tile, cp.async) ----
__global__ void __launch_bounds__(512, 1) layer_kernel(
    const float* __restrict__ xin, float* __restrict__ xout,
    const float* __restrict__ imgWd, const float* __restrict__ bdl,
    const float* __restrict__ imgWr, const float* __restrict__ brl,
    int d, int Lout, int layer)
{
    extern __shared__ float sm[];
    float* Xs = sm;                    // 256 x 128 (tf32 swizzled)
    float* Wb = sm + 256 * 128;        // 2 x 8192 floats (ping-pong weights)

    const int tid = threadIdx.x;
    const int w = tid >> 5, lane = tid & 31, g = lane >> 2, q = lane & 3;
    const int b = blockIdx.y;
    const int t0 = blockIdx.x * 128;
    const float* xb = xin + (size_t)b * WD * TFULL;

    // stage phase-1 weight chunk 0 (async)
    {
        const float4* src = (const float4*)(imgWd + (size_t)layer * 8 * 8192);
        float4* dst = (float4*)Wb;
        for (int i = tid; i < 2048; i += 512) cp16(dst + i, src + i);
        CP_COMMIT;
    }

    // ---- X tile: tap0 rows 0..127, tap1 rows 128..255
    for (int i = tid; i < 128 * 32; i += 512) {
        int k = i >> 5, t4 = (i & 31) << 2;
        int tg = t0 + t4; if (tg > TFULL - 4) tg = TFULL - 4;
        float4 v = *(const float4*)(xb + (size_t)k * TFULL + tg);
        store4_128(Xs + k * 128, t4, FB(k & 3), v);
    }
    if ((d & 3) == 0) {
        for (int i = tid; i < 128 * 32; i += 512) {
            int k = i >> 5, t4 = (i & 31) << 2;
            int tg = t0 + t4 + d; if (tg > TFULL - 4) tg = TFULL - 4;
            float4 v = *(const float4*)(xb + (size_t)k * TFULL + tg);
            store4_128(Xs + (128 + k) * 128, t4, FB(k & 3), v);
        }
    } else {
        for (int i = tid; i < 128 * 128; i += 512) {
            int k = i >> 7, t = i & 127;
            int tg = t0 + t + d; if (tg > TFULL - 1) tg = TFULL - 1;
            Xs[(128 + k) * 128 + swzB128(t, FB(k & 3))] =
                __uint_as_float(f2tf(xb[(size_t)k * TFULL + tg]));
        }
    }

    const int m0 = (w & 3) * 64, n0 = (w >> 2) * 32;
    const int fq = FB(q);
    const int offA0 = m0 + (((2 * g)     ^ fq) << 2);
    const int offA1 = m0 + (((2 * g + 1) ^ fq) << 2);
    const int offB  = ((n0 >> 6) << 6) + (((g * 2 + ((n0 & 63) >> 5)) ^ fq) << 2);

    float acc[4][4][4];
#pragma unroll
    for (int mf = 0; mf < 4; ++mf)
#pragma unroll
        for (int nf = 0; nf < 4; ++nf)
#pragma unroll
            for (int e = 0; e < 4; ++e) acc[mf][nf][e] = 0.0f;

    // ---- Phase 1: 8 K-chunks, double-buffered weights
    for (int c = 0; c < 8; ++c) {
        CP_WAIT0;
        __syncthreads();
        if (c < 7) {
            const float4* src = (const float4*)(imgWd + (size_t)(layer * 8 + c + 1) * 8192);
            float4* dst = (float4*)(Wb + ((c + 1) & 1) * 8192);
            for (int i = tid; i < 2048; i += 512) cp16(dst + i, src + i);
            CP_COMMIT;
        } else {
            const float4* src = (const float4*)(imgWr + (size_t)layer * 4 * 4096);
            float4* dst = (float4*)(Wb);                 // phase2 chunk0 -> buf0
            for (int i = tid; i < 1024; i += 512) cp16(dst + i, src + i);
            CP_COMMIT;
        }
        const unsigned* WuC = (const unsigned*)(Wb + (c & 1) * 8192);
#pragma unroll
        for (int kk = 0; kk < 32; kk += 8) {
            const unsigned* W1 = WuC + (kk + q) * 256;
            const unsigned* W2 = W1 + 4 * 256;
            uint4 a0 = *(const uint4*)(W1 + offA0);
            uint4 a1 = *(const uint4*)(W1 + offA1);
            uint4 a2 = *(const uint4*)(W2 + offA0);
            uint4 a3 = *(const uint4*)(W2 + offA1);
            const unsigned* B1 = (const unsigned*)Xs + (c * 32 + kk + q) * 128;
            uint4 b0 = *(const uint4*)(B1 + offB);
            uint4 b1 = *(const uint4*)(B1 + 4 * 128 + offB);
            unsigned A[4][4] = {{a0.x, a0.y, a2.x, a2.y}, {a0.z, a0.w, a2.z, a2.w},
                                {a1.x, a1.y, a3.x, a3.y}, {a1.z, a1.w, a3.z, a3.w}};
            unsigned Bf[4][2] = {{b0.x, b1.x}, {b0.y, b1.y}, {b0.z, b1.z}, {b0.w, b1.w}};
#pragma unroll
            for (int mf = 0; mf < 4; ++mf)
#pragma unroll
                for (int nf = 0; nf < 4; ++nf)
                    mma8(acc[mf][nf], A[mf], Bf[nf]);
        }
    }

    // ---- gate: hi warps (m0>=128) write sigmoid into rows 0..127
    if (m0 >= 128) {
#pragma unroll
        for (int mf = 0; mf < 4; ++mf) {
            int r0 = m0 + mf * 16 + g;
            float b0v = bdl[r0], b1v = bdl[r0 + 8];
#pragma unroll
            for (int nf = 0; nf < 4; ++nf) {
                int c0 = n0 + nf * 8 + q * 2;
#pragma unroll
                for (int e = 0; e < 4; ++e) {
                    int row = r0 + ((e >= 2) ? 8 : 0);
                    int col = c0 + (e & 1);
                    float v = acc[mf][nf][e] + ((e >= 2) ? b1v : b0v);
                    float s = __fdividef(1.0f, 1.0f + __expf(-v));
                    Xs[(row - 128) * 128 + swzB128(col, FB(row & 3))] = s;
                }
            }
        }
    }
    __syncthreads();
    if (m0 < 128) {
#pragma unroll
        for (int mf = 0; mf < 4; ++mf) {
            int r0 = m0 + mf * 16 + g;
            float b0v = bdl[r0], b1v = bdl[r0 + 8];
#pragma unroll
            for (int nf = 0; nf < 4; ++nf) {
                int c0 = n0 + nf * 8 + q * 2;
#pragma unroll
                for (int e = 0; e < 4; ++e) {
                    int row = r0 + ((e >= 2) ? 8 : 0);
                    int col = c0 + (e & 1);
                    float v = acc[mf][nf][e] + ((e >= 2) ? b1v : b0v);
                    int off = row * 128 + swzB128(col, FB(row & 3));
                    float av = tanh_fast(v) * Xs[off];
                    Xs[off] = __uint_as_float(f2tf(av));
                }
            }
        }
    }
    __syncthreads();

    // ---- store acts tail slice
    {
        const int tail = Lout - FO;
        if (t0 + 128 > tail) {
            float* ag = g_acts + (size_t)(b * NL + layer) * WD * FOP;
            for (int i = tid; i < 128 * 128; i += 512) {
                int cc = i >> 7, t = i & 127, tg = t0 + t;
                if (tg >= tail && tg < Lout)
                    ag[(size_t)cc * FOP + (tg - tail)] = Xs[cc * 128 + swzB128(t, FB(cc & 3))];
            }
        }
    }

    // ---- Phase 2: res GEMM (M=128, K=128), 4 chunks, double-buffered
    const int m0b = (w & 3) * 32;
    const int offA2 = m0b + ((g ^ F2(q)) << 2);
    float ac2[2][4][4];
#pragma unroll
    for (int mf = 0; mf < 2; ++mf)
#pragma unroll
        for (int nf = 0; nf < 4; ++nf)
#pragma unroll
            for (int e = 0; e < 4; ++e) ac2[mf][nf][e] = 0.0f;

    for (int c2 = 0; c2 < 4; ++c2) {
        CP_WAIT0;
        __syncthreads();
        if (c2 < 3) {
            const float4* src = (const float4*)(imgWr + (size_t)(layer * 4 + c2 + 1) * 4096);
            float4* dst = (float4*)(Wb + ((c2 + 1) & 1) * 8192);
            for (int i = tid; i < 1024; i += 512) cp16(dst + i, src + i);
            CP_COMMIT;
        }
        const unsigned* WuC = (const unsigned*)(Wb + (c2 & 1) * 8192);
#pragma unroll
        for (int kk = 0; kk < 32; kk += 8) {
            const unsigned* W1 = WuC + (kk + q) * 128;
            const unsigned* W2 = W1 + 4 * 128;
            uint4 a0 = *(const uint4*)(W1 + offA2);
            uint4 a2 = *(const uint4*)(W2 + offA2);
            const unsigned* B1 = (const unsigned*)Xs + (c2 * 32 + kk + q) * 128;
            uint4 b0 = *(const uint4*)(B1 + offB);
            uint4 b1 = *(const uint4*)(B1 + 4 * 128 + offB);
            unsigned A2r[2][4] = {{a0.x, a0.y, a2.x, a2.y}, {a0.z, a0.w, a2.z, a2.w}};
            unsigned Bf[4][2] = {{b0.x, b1.x}, {b0.y, b1.y}, {b0.z, b1.z}, {b0.w, b1.w}};
#pragma unroll
            for (int mf = 0; mf < 2; ++mf)
#pragma unroll
                for (int nf = 0; nf < 4; ++nf)
                    mma8(ac2[mf][nf], A2r[mf], Bf[nf]);
        }
    }

    // ---- stage res (+bias) linear into rows 128..255, then residual + store
    float* Rs = Xs + 128 * 128;
#pragma unroll
    for (int mf = 0; mf < 2; ++mf) {
        int r0 = m0b + mf * 16 + g;
        float br0 = brl[r0], br1 = brl[r0 + 8];
#pragma unroll
        for (int nf = 0; nf < 4; ++nf) {
            int c0 = n0 + nf * 8 + q * 2;
#pragma unroll
            for (int e = 0; e < 4; ++e) {
                int row = r0 + ((e >= 2) ? 8 : 0);
                int col = c0 + (e & 1);
                Rs[row * 128 + col] = ac2[mf][nf][e] + ((e >= 2) ? br1 : br0);
            }
        }
    }
    __syncthreads();

    float* xo = xout + (size_t)b * WD * TFULL;
    for (int i = tid; i < 128 * 128; i += 512) {
        int cc = i >> 7, t = i & 127, tg = t0 + t;
        if (tg < Lout)
            xo[(size_t)cc * TFULL + tg] = Rs[cc * 128 + t] + xb[(size_t)cc * TFULL + tg + d];
    }
}

// ---------------- generic GEMM (512 thr, 128-t tile, full cp.async pipe) ----
__global__ void __launch_bounds__(512, 1) gemm_mma(
    const float* __restrict__ X, const float* __restrict__ imgW,
    const float* __restrict__ bias, int nbias, int doRelu,
    int K, int NO, float* __restrict__ out, int ostride, int olimit)
{
    extern __shared__ float sm[];
    float* Xst = sm;                   // 2 x (32*128) floats
    float* Wb  = sm + 2 * 4096;        // 2 x 8192 floats

    const int tid = threadIdx.x;
    const int w = tid >> 5, lane = tid & 31, g = lane >> 2, q = lane & 3;
    const int b = blockIdx.z, ot = blockIdx.y;
    const int t0 = blockIdx.x * 128;
    const float* Xb = X + (size_t)b * K * FOP;
    const int NC = K >> 5;

    const int m0 = (w & 3) * 64, n0 = (w >> 2) * 32;
    const int fq = FB(q);
    const int offA0 = m0 + (((2 * g)     ^ fq) << 2);
    const int offA1 = m0 + (((2 * g + 1) ^ fq) << 2);
    const int offB  = ((n0 >> 6) << 6) + (((g * 2 + ((n0 & 63) >> 5)) ^ fq) << 2);

    // X-chunk loader: thread handles 2 float4 per chunk
    const int xk0 = tid >> 5, xt4 = (tid & 31) << 2;          // rows 0..15
    const int xk1 = xk0 + 16;

    // initial: stage W(0) async, load+store X(0)
    {
        const float4* src = (const float4*)(imgW + (size_t)(ot * NC) * 8192);
        float4* dst = (float4*)Wb;
        for (int i = tid; i < 2048; i += 512) cp16(dst + i, src + i);
        CP_COMMIT;
        float4 v0 = *(const float4*)(Xb + (size_t)xk0 * FOP + t0 + xt4);
        float4 v1 = *(const float4*)(Xb + (size_t)xk1 * FOP + t0 + xt4);
        store4_128(Xst + xk0 * 128, xt4, FB(xk0 & 3), v0);
        store4_128(Xst + xk1 * 128, xt4, FB(xk1 & 3), v1);
    }

    float acc[4][4][4];
#pragma unroll
    for (int mf = 0; mf < 4; ++mf)
#pragma unroll
        for (int nf = 0; nf < 4; ++nf)
#pragma unroll
            for (int e = 0; e < 4; ++e) acc[mf][nf][e] = 0.0f;

    for (int c = 0; c < NC; ++c) {
        CP_WAIT0;
        __syncthreads();
        if (c + 1 < NC) {
            const float4* src = (const float4*)(imgW + (size_t)(ot * NC + c + 1) * 8192);
            float4* dst = (float4*)(Wb + ((c + 1) & 1) * 8192);
            for (int i = tid; i < 2048; i += 512) cp16(dst + i, src + i);
            CP_COMMIT;
            int kbase = (c + 1) * 32;
            float4 v0 = *(const float4*)(Xb + (size_t)(kbase + xk0) * FOP + t0 + xt4);
            float4 v1 = *(const float4*)(Xb + (size_t)(kbase + xk1) * FOP + t0 + xt4);
            float* xdst = Xst + ((c + 1) & 1) * 4096;
            store4_128(xdst + xk0 * 128, xt4, FB(xk0 & 3), v0);
            store4_128(xdst + xk1 * 128, xt4, FB(xk1 & 3), v1);
        }
        const unsigned* WuC = (const unsigned*)(Wb + (c & 1) * 8192);
        const unsigned* Bbase = (const unsigned*)(Xst + (c & 1) * 4096);
#pragma unroll
        for (int kk = 0; kk < 32; kk += 8) {
            const unsigned* W1 = WuC + (kk + q) * 256;
            const unsigned* W2 = W1 + 4 * 256;
            uint4 a0 = *(const uint4*)(W1 + offA0);
            uint4 a1 = *(const uint4*)(W1 + offA1);
            uint4 a2 = *(const uint4*)(W2 + offA0);
            uint4 a3 = *(const uint4*)(W2 + offA1);
            const unsigned* B1 = Bbase + (kk + q) * 128;
            uint4 b0 = *(const uint4*)(B1 + offB);
            uint4 b1 = *(const uint4*)(B1 + 4 * 128 + offB);
            unsigned A[4][4] = {{a0.x, a0.y, a2.x, a2.y}, {a0.z, a0.w, a2.z, a2.w},
                                {a1.x, a1.y, a3.x, a3.y}, {a1.z, a1.w, a3.z, a3.w}};
            unsigned Bf[4][2] = {{b0.x, b1.x}, {b0.y, b1.y}, {b0.z, b1.z}, {b0.w, b1.w}};
#pragma unroll
            for (int mf = 0; mf < 4; ++mf)
#pragma unroll
                for (int nf = 0; nf < 4; ++nf)
                    mma8(acc[mf][nf], A[mf], Bf[nf]);
        }
    }

    // epilogue
#pragma unroll
    for (int mf = 0; mf < 4; ++mf) {
        int r0 = ot * 256 + m0 + mf * 16 + g;
        float bs0 = 0.0f, bs1 = 0.0f;
        for (int i = 0; i < nbias; ++i) {
            bs0 += bias[(size_t)i * NO + r0];
            bs1 += bias[(size_t)i * NO + r0 + 8];
        }
#pragma unroll
        for (int nf = 0; nf < 4; ++nf) {
            int c0 = t0 + n0 + nf * 8 + q * 2;
#pragma unroll
            for (int e = 0; e < 4; ++e) {
                int row = r0 + ((e >= 2) ? 8 : 0);
                int t = c0 + (e & 1);
                float v = acc[mf][nf][e] + ((e >= 2) ? bs1 : bs0);
                if (doRelu) v = fmaxf(v, 0.0f);
                if (t < olimit)
                    out[((size_t)b * NO + row) * ostride + t] = v;
            }
        }
    }
}

// ---------------- host launcher ---------------------------------------------
extern "C" void kernel_launch(void* const* d_in, const int* in_sizes, int n_in,
                              void* d_out, int out_size)
{
    const int*   y   = (const int*)d_in[0];
    const float* emb = (const float*)d_in[1];
    const float* Wd  = (const float*)d_in[2];
    const float* bd  = (const float*)d_in[3];
    const float* Wr  = (const float*)d_in[4];
    const float* br  = (const float*)d_in[5];
    const float* Ws  = (const float*)d_in[6];
    const float* bs  = (const float*)d_in[7];
    const float* p1  = (const float*)d_in[8];
    const float* p2  = (const float*)d_in[9];
    float* out = (float*)d_out;

    static const int dil[NL] = {1, 2, 4, 8, 16, 32, 64, 128, 256, 512,
                                1, 2, 4, 8, 16, 32, 64, 128, 256, 512};

    size_t smemL = (size_t)(256 * 128 + 2 * 8192) * sizeof(float);    // 196,608 B
    size_t smemG = (size_t)(2 * 4096 + 2 * 8192) * sizeof(float);     //  98,304 B
    cudaFuncSetAttribute(layer_kernel, cudaFuncAttributeMaxDynamicSharedMemorySize, (int)smemL);
    cudaFuncSetAttribute(gemm_mma,     cudaFuncAttributeMaxDynamicSharedMemorySize, (int)smemG);

    float *x0, *x1, *acts, *skip, *h;
    float *iWd, *iWr, *iWs, *iP1, *iP2;
    cudaGetSymbolAddress((void**)&x0,   g_x0);
    cudaGetSymbolAddress((void**)&x1,   g_x1);
    cudaGetSymbolAddress((void**)&acts, g_acts);
    cudaGetSymbolAddress((void**)&skip, g_skip);
    cudaGetSymbolAddress((void**)&h,    g_h);
    cudaGetSymbolAddress((void**)&iWd,  g_imgWd);
    cudaGetSymbolAddress((void**)&iWr,  g_imgWr);
    cudaGetSymbolAddress((void**)&iWs,  g_imgWs);
    cudaGetSymbolAddress((void**)&iP1,  g_imgP1);
    cudaGetSymbolAddress((void**)&iP2,  g_imgP2);

    // one-time weight images (tf32 + fragment permutation + swizzle)
    prep64<<<5120, 256>>>(Wd, 5120, 256, iWd);
    prep32<<<1280, 256>>>(Wr, 2560, iWr);
    prep64<<<5120, 256>>>(Ws, 2560, 512, iWs);
    prep64<<<1024, 256>>>(p1, 512, 512, iP1);
    prep64<<<512,  256>>>(p2, 512, 256, iP2);

    embed_kernel<<<dim3(TFULL / 32, 8), 256>>>(y, emb, x0);

    float* xin = x0;
    float* xout = x1;
    int Tin = TFULL;
    for (int i = 0; i < NL; ++i) {
        int d = dil[i];
        int Lout = Tin - d;
        dim3 grid((Lout + 127) / 128, 8);
        layer_kernel<<<grid, 512, smemL>>>(
            xin, xout,
            iWd, bd + (size_t)i * 2 * WD,
            iWr, br + (size_t)i * WD,
            d, Lout, i);
        float* tmp = xin; xin = xout; xout = tmp;
        Tin = Lout;
    }

    dim3 g1((FOP + 127) / 128, 2, 8);
    gemm_mma<<<g1, 512, smemG>>>(acts, iWs, bs, NL, 1, NL * WD, 512, skip, FOP, FOP);
    gemm_mma<<<g1, 512, smemG>>>(skip, iP1, nullptr, 0, 1, 512, 512, h, FOP, FOP);
    dim3 g3((FOP + 127) / 128, 1, 8);
    gemm_mma<<<g3, 512, smemG>>>(h, iP2, nullptr, 0, 0, 512, 256, out, FO, FO);
}

// round 7
// speedup vs baseline: 2.6151x; 1.0002x over previous
#include <cuda_runtime.h>
#include <math.h>

#define WD 128
#define FO 6145
#define FOP 6208          // padded time stride for scratch (mult of 64)
#define TFULL 8192
#define NL 20

// swizzle functions (XOR on float4-chunk index; keep LDS.128 conflict-free)
#define FB(k) ((((k)&1)<<2) | (((k)>>1)&1))   // 0,4,1,5  (64-wide rows)
#define F2(k) ((((k)&1)<<2) | ((k)&2))        // 0,4,2,6  (32-wide A blocks)

// ---------------- scratch (device globals; no allocations allowed) ----------
__device__ __align__(256) float g_x0[(size_t)8 * WD * TFULL + 2048];
__device__ __align__(256) float g_x1[(size_t)8 * WD * TFULL + 2048];
__device__ __align__(256) float g_acts[(size_t)8 * NL * WD * FOP + 512];
__device__ __align__(256) float g_skip[(size_t)8 * 512 * FOP + 512];
__device__ __align__(256) float g_h[(size_t)8 * 512 * FOP + 512];
__device__ __align__(256) float g_imgWd[(size_t)NL * 256 * 256];
__device__ __align__(256) float g_imgWr[(size_t)NL * 128 * 128];
__device__ __align__(256) float g_imgWs[(size_t)2560 * 512];
__device__ __align__(256) float g_imgP1[(size_t)512 * 512];
__device__ __align__(256) float g_imgP2[(size_t)512 * 256];

// ---------------- helpers ---------------------------------------------------
__device__ __forceinline__ unsigned f2tf(float x) {
    unsigned u;
    asm("cvt.rna.tf32.f32 %0, %1;" : "=r"(u) : "f"(x));
    return u;
}
__device__ __forceinline__ void mma8(float* c, const unsigned a[4], const unsigned b[2]) {
    asm volatile("mma.sync.aligned.m16n8k8.row.col.f32.tf32.tf32.f32 "
                 "{%0,%1,%2,%3}, {%4,%5,%6,%7}, {%8,%9}, {%0,%1,%2,%3};\n"
                 : "+f"(c[0]), "+f"(c[1]), "+f"(c[2]), "+f"(c[3])
                 : "r"(a[0]), "r"(a[1]), "r"(a[2]), "r"(a[3]),
                   "r"(b[0]), "r"(b[1]));
}
__device__ __forceinline__ float tanh_fast(float v) {
    float t;
    asm("tanh.approx.f32 %0, %1;" : "=f"(t) : "f"(v));
    return t;
}
__device__ __forceinline__ void cp16(float4* dst_smem, const float4* src) {
    unsigned a = (unsigned)__cvta_generic_to_shared(dst_smem);
    asm volatile("cp.async.cg.shared.global [%0], [%1], 16;" :: "r"(a), "l"(src));
}
#define CP_COMMIT asm volatile("cp.async.commit_group;")
#define CP_WAIT0  asm volatile("cp.async.wait_group 0;")

// swizzled float offset of time-index t within a 64-float row, row mod-4 = k
__device__ __forceinline__ int swzB(int t, int fk) {
    int p = ((t & 7) << 3) | (t >> 3);
    return ((((p >> 2) ^ fk)) << 2) | (p & 3);
}
// swizzled offset within a 128-float row
__device__ __forceinline__ int swzB128(int t, int fk) {
    return ((t >> 6) << 6) + swzB(t & 63, fk);
}
// store 4 consecutive t values (t4 aligned to 4, t4 in [0,64)) into swizzled 64-row
__device__ __forceinline__ void store4(float* row, int t4, int fk, float4 v) {
    int p0 = ((t4 & 7) << 3) | (t4 >> 3);
    int c0 = p0 >> 2, lo = p0 & 3;
    row[((((c0 + 0) ^ fk)) << 2) | lo] = __uint_as_float(f2tf(v.x));
    row[((((c0 + 2) ^ fk)) << 2) | lo] = __uint_as_float(f2tf(v.y));
    row[((((c0 + 4) ^ fk)) << 2) | lo] = __uint_as_float(f2tf(v.z));
    row[((((c0 + 6) ^ fk)) << 2) | lo] = __uint_as_float(f2tf(v.w));
}
// same for 128-wide rows
__device__ __forceinline__ void store4_128(float* row, int t4, int fk, float4 v) {
    store4(row + ((t4 >> 6) << 6), t4 & 63, fk, v);
}

// ---------------- weight image prep (one-time per launch) -------------------
__global__ void __launch_bounds__(256) prep64(
    const float* __restrict__ W, int K, int NO, float* __restrict__ img)
{
    int idx = blockIdx.x * 256 + threadIdx.x;
    if (idx >= K * NO) return;
    int k = idx / NO, o = idx - k * NO;
    int ot = o >> 8, m = o & 255;
    int ch = k >> 5, kk = k & 31;
    int p = ((m & 7) << 3) | ((m >> 3) & 7);
    int pos = (m & ~63) + ((((p >> 2) ^ FB(kk & 3))) << 2) + (p & 3);
    img[((size_t)(ot * (K >> 5) + ch) * 32 + kk) * 256 + pos] =
        __uint_as_float(f2tf(W[idx]));
}
__global__ void __launch_bounds__(256) prep32(
    const float* __restrict__ W, int K, float* __restrict__ img)
{
    int idx = blockIdx.x * 256 + threadIdx.x;
    if (idx >= K * 128) return;
    int k = idx >> 7, m = idx & 127;
    int ch = k >> 5, kk = k & 31;
    int p = ((m & 7) << 2) | ((m >> 3) & 3);
    int pos = (m & ~31) + ((((p >> 2) ^ F2(kk & 3))) << 2) + (p & 3);
    img[((size_t)ch * 32 + kk) * 128 + pos] = __uint_as_float(f2tf(W[idx]));
}

// ---------------- embedding -------------------------------------------------
__global__ void __launch_bounds__(256) embed_kernel(
    const int* __restrict__ y, const float* __restrict__ emb, float* __restrict__ x)
{
    int b = blockIdx.y;
    int t = blockIdx.x * 32 + (threadIdx.x & 31);
    int cg = threadIdx.x >> 5;
    int idx = y[b * TFULL + t];
    const float* er = emb + (size_t)idx * WD;
    float* xb = x + (size_t)b * WD * TFULL;
#pragma unroll
    for (int j = 0; j < 16; ++j) {
        int c = cg * 16 + j;
        xb[(size_t)c * TFULL + t] = er[c];
    }
}

// ---------------- fused per-layer kernel (512 thr, 128-t tile, cp.async) ----
__global__ void __launch_bounds__(512, 1) layer_kernel(
    const float* __restrict__ xin, float* __restrict__ xout,
    const float* __restrict__ imgWd, const float* __restrict__ bdl,
    const float* __restrict__ imgWr, const float* __restrict__ brl,
    int d, int Lout, int layer)
{
    extern __shared__ float sm[];
    float* Xs = sm;                    // 256 x 128 (tf32 swizzled)
    float* Wb = sm + 256 * 128;        // 2 x 8192 floats (ping-pong weights)

    const int tid = threadIdx.x;
    const int w = tid >> 5, lane = tid & 31, g = lane >> 2, q = lane & 3;
    const int b = blockIdx.y;
    const int t0 = blockIdx.x * 128;
    const float* xb = xin + (size_t)b * WD * TFULL;

    // stage phase-1 weight chunk 0 (async)
    {
        const float4* src = (const float4*)(imgWd + (size_t)layer * 8 * 8192);
        float4* dst = (float4*)Wb;
        for (int i = tid; i < 2048; i += 512) cp16(dst + i, src + i);
        CP_COMMIT;
    }

    // ---- X tile: tap0 rows 0..127, tap1 rows 128..255
    for (int i = tid; i < 128 * 32; i += 512) {
        int k = i >> 5, t4 = (i & 31) << 2;
        int tg = t0 + t4; if (tg > TFULL - 4) tg = TFULL - 4;
        float4 v = *(const float4*)(xb + (size_t)k * TFULL + tg);
        store4_128(Xs + k * 128, t4, FB(k & 3), v);
    }
    if ((d & 3) == 0) {
        for (int i = tid; i < 128 * 32; i += 512) {
            int k = i >> 5, t4 = (i & 31) << 2;
            int tg = t0 + t4 + d; if (tg > TFULL - 4) tg = TFULL - 4;
            float4 v = *(const float4*)(xb + (size_t)k * TFULL + tg);
            store4_128(Xs + (128 + k) * 128, t4, FB(k & 3), v);
        }
    } else {
        for (int i = tid; i < 128 * 128; i += 512) {
            int k = i >> 7, t = i & 127;
            int tg = t0 + t + d; if (tg > TFULL - 1) tg = TFULL - 1;
            Xs[(128 + k) * 128 + swzB128(t, FB(k & 3))] =
                __uint_as_float(f2tf(xb[(size_t)k * TFULL + tg]));
        }
    }

    const int m0 = (w & 3) * 64, n0 = (w >> 2) * 32;
    const int fq = FB(q);
    const int offA0 = m0 + (((2 * g)     ^ fq) << 2);
    const int offA1 = m0 + (((2 * g + 1) ^ fq) << 2);
    const int offB  = ((n0 >> 6) << 6) + (((g * 2 + ((n0 & 63) >> 5)) ^ fq) << 2);

    float acc[4][4][4];
#pragma unroll
    for (int mf = 0; mf < 4; ++mf)
#pragma unroll
        for (int nf = 0; nf < 4; ++nf)
#pragma unroll
            for (int e = 0; e < 4; ++e) acc[mf][nf][e] = 0.0f;

    // ---- Phase 1: 8 K-chunks, double-buffered weights
    for (int c = 0; c < 8; ++c) {
        CP_WAIT0;
        __syncthreads();
        if (c < 7) {
            const float4* src = (const float4*)(imgWd + (size_t)(layer * 8 + c + 1) * 8192);
            float4* dst = (float4*)(Wb + ((c + 1) & 1) * 8192);
            for (int i = tid; i < 2048; i += 512) cp16(dst + i, src + i);
            CP_COMMIT;
        } else {
            const float4* src = (const float4*)(imgWr + (size_t)layer * 4 * 4096);
            float4* dst = (float4*)(Wb);                 // phase2 chunk0 -> buf0
            for (int i = tid; i < 1024; i += 512) cp16(dst + i, src + i);
            CP_COMMIT;
        }
        const unsigned* WuC = (const unsigned*)(Wb + (c & 1) * 8192);
#pragma unroll
        for (int kk = 0; kk < 32; kk += 8) {
            const unsigned* W1 = WuC + (kk + q) * 256;
            const unsigned* W2 = W1 + 4 * 256;
            uint4 a0 = *(const uint4*)(W1 + offA0);
            uint4 a1 = *(const uint4*)(W1 + offA1);
            uint4 a2 = *(const uint4*)(W2 + offA0);
            uint4 a3 = *(const uint4*)(W2 + offA1);
            const unsigned* B1 = (const unsigned*)Xs + (c * 32 + kk + q) * 128;
            uint4 b0 = *(const uint4*)(B1 + offB);
            uint4 b1 = *(const uint4*)(B1 + 4 * 128 + offB);
            unsigned A[4][4] = {{a0.x, a0.y, a2.x, a2.y}, {a0.z, a0.w, a2.z, a2.w},
                                {a1.x, a1.y, a3.x, a3.y}, {a1.z, a1.w, a3.z, a3.w}};
            unsigned Bf[4][2] = {{b0.x, b1.x}, {b0.y, b1.y}, {b0.z, b1.z}, {b0.w, b1.w}};
#pragma unroll
            for (int mf = 0; mf < 4; ++mf)
#pragma unroll
                for (int nf = 0; nf < 4; ++nf)
                    mma8(acc[mf][nf], A[mf], Bf[nf]);
        }
    }

    // ---- gate: hi warps (m0>=128) write sigmoid into rows 0..127
    if (m0 >= 128) {
#pragma unroll
        for (int mf = 0; mf < 4; ++mf) {
            int r0 = m0 + mf * 16 + g;
            float b0v = bdl[r0], b1v = bdl[r0 + 8];
#pragma unroll
            for (int nf = 0; nf < 4; ++nf) {
                int c0 = n0 + nf * 8 + q * 2;
#pragma unroll
                for (int e = 0; e < 4; ++e) {
                    int row = r0 + ((e >= 2) ? 8 : 0);
                    int col = c0 + (e & 1);
                    float v = acc[mf][nf][e] + ((e >= 2) ? b1v : b0v);
                    float s = __fdividef(1.0f, 1.0f + __expf(-v));
                    Xs[(row - 128) * 128 + swzB128(col, FB(row & 3))] = s;
                }
            }
        }
    }
    __syncthreads();
    if (m0 < 128) {
#pragma unroll
        for (int mf = 0; mf < 4; ++mf) {
            int r0 = m0 + mf * 16 + g;
            float b0v = bdl[r0], b1v = bdl[r0 + 8];
#pragma unroll
            for (int nf = 0; nf < 4; ++nf) {
                int c0 = n0 + nf * 8 + q * 2;
#pragma unroll
                for (int e = 0; e < 4; ++e) {
                    int row = r0 + ((e >= 2) ? 8 : 0);
                    int col = c0 + (e & 1);
                    float v = acc[mf][nf][e] + ((e >= 2) ? b1v : b0v);
                    int off = row * 128 + swzB128(col, FB(row & 3));
                    float av = tanh_fast(v) * Xs[off];
                    Xs[off] = __uint_as_float(f2tf(av));
                }
            }
        }
    }
    __syncthreads();

    // ---- store acts tail slice
    {
        const int tail = Lout - FO;
        if (t0 + 128 > tail) {
            float* ag = g_acts + (size_t)(b * NL + layer) * WD * FOP;
            for (int i = tid; i < 128 * 128; i += 512) {
                int cc = i >> 7, t = i & 127, tg = t0 + t;
                if (tg >= tail && tg < Lout)
                    ag[(size_t)cc * FOP + (tg - tail)] = Xs[cc * 128 + swzB128(t, FB(cc & 3))];
            }
        }
    }

    // ---- Phase 2: res GEMM (M=128, K=128), 4 chunks, double-buffered
    const int m0b = (w & 3) * 32;
    const int offA2 = m0b + ((g ^ F2(q)) << 2);
    float ac2[2][4][4];
#pragma unroll
    for (int mf = 0; mf < 2; ++mf)
#pragma unroll
        for (int nf = 0; nf < 4; ++nf)
#pragma unroll
            for (int e = 0; e < 4; ++e) ac2[mf][nf][e] = 0.0f;

    for (int c2 = 0; c2 < 4; ++c2) {
        CP_WAIT0;
        __syncthreads();
        if (c2 < 3) {
            const float4* src = (const float4*)(imgWr + (size_t)(layer * 4 + c2 + 1) * 4096);
            float4* dst = (float4*)(Wb + ((c2 + 1) & 1) * 8192);
            for (int i = tid; i < 1024; i += 512) cp16(dst + i, src + i);
            CP_COMMIT;
        }
        const unsigned* WuC = (const unsigned*)(Wb + (c2 & 1) * 8192);
#pragma unroll
        for (int kk = 0; kk < 32; kk += 8) {
            const unsigned* W1 = WuC + (kk + q) * 128;
            const unsigned* W2 = W1 + 4 * 128;
            uint4 a0 = *(const uint4*)(W1 + offA2);
            uint4 a2 = *(const uint4*)(W2 + offA2);
            const unsigned* B1 = (const unsigned*)Xs + (c2 * 32 + kk + q) * 128;
            uint4 b0 = *(const uint4*)(B1 + offB);
            uint4 b1 = *(const uint4*)(B1 + 4 * 128 + offB);
            unsigned A2r[2][4] = {{a0.x, a0.y, a2.x, a2.y}, {a0.z, a0.w, a2.z, a2.w}};
            unsigned Bf[4][2] = {{b0.x, b1.x}, {b0.y, b1.y}, {b0.z, b1.z}, {b0.w, b1.w}};
#pragma unroll
            for (int mf = 0; mf < 2; ++mf)
#pragma unroll
                for (int nf = 0; nf < 4; ++nf)
                    mma8(ac2[mf][nf], A2r[mf], Bf[nf]);
        }
    }

    // ---- stage res (+bias) linear into rows 128..255, then residual + store
    float* Rs = Xs + 128 * 128;
#pragma unroll
    for (int mf = 0; mf < 2; ++mf) {
        int r0 = m0b + mf * 16 + g;
        float br0 = brl[r0], br1 = brl[r0 + 8];
#pragma unroll
        for (int nf = 0; nf < 4; ++nf) {
            int c0 = n0 + nf * 8 + q * 2;
#pragma unroll
            for (int e = 0; e < 4; ++e) {
                int row = r0 + ((e >= 2) ? 8 : 0);
                int col = c0 + (e & 1);
                Rs[row * 128 + col] = ac2[mf][nf][e] + ((e >= 2) ? br1 : br0);
            }
        }
    }
    __syncthreads();

    float* xo = xout + (size_t)b * WD * TFULL;
    for (int i = tid; i < 128 * 128; i += 512) {
        int cc = i >> 7, t = i & 127, tg = t0 + t;
        if (tg < Lout)
            xo[(size_t)cc * TFULL + tg] = Rs[cc * 128 + t] + xb[(size_t)cc * TFULL + tg + d];
    }
}

// ---------------- generic GEMM (512 thr, 128-t tile, full cp.async pipe) ----
__global__ void __launch_bounds__(512, 1) gemm_mma(
    const float* __restrict__ X, const float* __restrict__ imgW,
    const float* __restrict__ bias, int nbias, int doRelu,
    int K, int NO, float* __restrict__ out, int ostride, int olimit)
{
    extern __shared__ float sm[];
    float* Xst = sm;                   // 2 x (32*128) floats
    float* Wb  = sm + 2 * 4096;        // 2 x 8192 floats

    const int tid = threadIdx.x;
    const int w = tid >> 5, lane = tid & 31, g = lane >> 2, q = lane & 3;
    const int b = blockIdx.z, ot = blockIdx.y;
    const int t0 = blockIdx.x * 128;
    const float* Xb = X + (size_t)b * K * FOP;
    const int NC = K >> 5;

    const int m0 = (w & 3) * 64, n0 = (w >> 2) * 32;
    const int fq = FB(q);
    const int offA0 = m0 + (((2 * g)     ^ fq) << 2);
    const int offA1 = m0 + (((2 * g + 1) ^ fq) << 2);
    const int offB  = ((n0 >> 6) << 6) + (((g * 2 + ((n0 & 63) >> 5)) ^ fq) << 2);

    // X-chunk loader: thread handles 2 float4 per chunk
    const int xk0 = tid >> 5, xt4 = (tid & 31) << 2;          // rows 0..15
    const int xk1 = xk0 + 16;

    // initial: stage W(0) async, load+store X(0)
    {
        const float4* src = (const float4*)(imgW + (size_t)(ot * NC) * 8192);
        float4* dst = (float4*)Wb;
        for (int i = tid; i < 2048; i += 512) cp16(dst + i, src + i);
        CP_COMMIT;
        float4 v0 = *(const float4*)(Xb + (size_t)xk0 * FOP + t0 + xt4);
        float4 v1 = *(const float4*)(Xb + (size_t)xk1 * FOP + t0 + xt4);
        store4_128(Xst + xk0 * 128, xt4, FB(xk0 & 3), v0);
        store4_128(Xst + xk1 * 128, xt4, FB(xk1 & 3), v1);
    }

    float acc[4][4][4];
#pragma unroll
    for (int mf = 0; mf < 4; ++mf)
#pragma unroll
        for (int nf = 0; nf < 4; ++nf)
#pragma unroll
            for (int e = 0; e < 4; ++e) acc[mf][nf][e] = 0.0f;

    for (int c = 0; c < NC; ++c) {
        CP_WAIT0;
        __syncthreads();
        if (c + 1 < NC) {
            const float4* src = (const float4*)(imgW + (size_t)(ot * NC + c + 1) * 8192);
            float4* dst = (float4*)(Wb + ((c + 1) & 1) * 8192);
            for (int i = tid; i < 2048; i += 512) cp16(dst + i, src + i);
            CP_COMMIT;
            int kbase = (c + 1) * 32;
            float4 v0 = *(const float4*)(Xb + (size_t)(kbase + xk0) * FOP + t0 + xt4);
            float4 v1 = *(const float4*)(Xb + (size_t)(kbase + xk1) * FOP + t0 + xt4);
            float* xdst = Xst + ((c + 1) & 1) * 4096;
            store4_128(xdst + xk0 * 128, xt4, FB(xk0 & 3), v0);
            store4_128(xdst + xk1 * 128, xt4, FB(xk1 & 3), v1);
        }
        const unsigned* WuC = (const unsigned*)(Wb + (c & 1) * 8192);
        const unsigned* Bbase = (const unsigned*)(Xst + (c & 1) * 4096);
#pragma unroll
        for (int kk = 0; kk < 32; kk += 8) {
            const unsigned* W1 = WuC + (kk + q) * 256;
            const unsigned* W2 = W1 + 4 * 256;
            uint4 a0 = *(const uint4*)(W1 + offA0);
            uint4 a1 = *(const uint4*)(W1 + offA1);
            uint4 a2 = *(const uint4*)(W2 + offA0);
            uint4 a3 = *(const uint4*)(W2 + offA1);
            const unsigned* B1 = Bbase + (kk + q) * 128;
            uint4 b0 = *(const uint4*)(B1 + offB);
            uint4 b1 = *(const uint4*)(B1 + 4 * 128 + offB);
            unsigned A[4][4] = {{a0.x, a0.y, a2.x, a2.y}, {a0.z, a0.w, a2.z, a2.w},
                                {a1.x, a1.y, a3.x, a3.y}, {a1.z, a1.w, a3.z, a3.w}};
            unsigned Bf[4][2] = {{b0.x, b1.x}, {b0.y, b1.y}, {b0.z, b1.z}, {b0.w, b1.w}};
#pragma unroll
            for (int mf = 0; mf < 4; ++mf)
#pragma unroll
                for (int nf = 0; nf < 4; ++nf)
                    mma8(acc[mf][nf], A[mf], Bf[nf]);
        }
    }

    // epilogue
#pragma unroll
    for (int mf = 0; mf < 4; ++mf) {
        int r0 = ot * 256 + m0 + mf * 16 + g;
        float bs0 = 0.0f, bs1 = 0.0f;
        for (int i = 0; i < nbias; ++i) {
            bs0 += bias[(size_t)i * NO + r0];
            bs1 += bias[(size_t)i * NO + r0 + 8];
        }
#pragma unroll
        for (int nf = 0; nf < 4; ++nf) {
            int c0 = t0 + n0 + nf * 8 + q * 2;
#pragma unroll
            for (int e = 0; e < 4; ++e) {
                int row = r0 + ((e >= 2) ? 8 : 0);
                int t = c0 + (e & 1);
                float v = acc[mf][nf][e] + ((e >= 2) ? bs1 : bs0);
                if (doRelu) v = fmaxf(v, 0.0f);
                if (t < olimit)
                    out[((size_t)b * NO + row) * ostride + t] = v;
            }
        }
    }
}

// ---------------- host launcher ---------------------------------------------
extern "C" void kernel_launch(void* const* d_in, const int* in_sizes, int n_in,
                              void* d_out, int out_size)
{
    const int*   y   = (const int*)d_in[0];
    const float* emb = (const float*)d_in[1];
    const float* Wd  = (const float*)d_in[2];
    const float* bd  = (const float*)d_in[3];
    const float* Wr  = (const float*)d_in[4];
    const float* br  = (const float*)d_in[5];
    const float* Ws  = (const float*)d_in[6];
    const float* bs  = (const float*)d_in[7];
    const float* p1  = (const float*)d_in[8];
    const float* p2  = (const float*)d_in[9];
    float* out = (float*)d_out;

    static const int dil[NL] = {1, 2, 4, 8, 16, 32, 64, 128, 256, 512,
                                1, 2, 4, 8, 16, 32, 64, 128, 256, 512};

    size_t smemL = (size_t)(256 * 128 + 2 * 8192) * sizeof(float);    // 196,608 B
    size_t smemG = (size_t)(2 * 4096 + 2 * 8192) * sizeof(float);     //  98,304 B
    cudaFuncSetAttribute(layer_kernel, cudaFuncAttributeMaxDynamicSharedMemorySize, (int)smemL);
    cudaFuncSetAttribute(gemm_mma,     cudaFuncAttributeMaxDynamicSharedMemorySize, (int)smemG);

    float *x0, *x1, *acts, *skip, *h;
    float *iWd, *iWr, *iWs, *iP1, *iP2;
    cudaGetSymbolAddress((void**)&x0,   g_x0);
    cudaGetSymbolAddress((void**)&x1,   g_x1);
    cudaGetSymbolAddress((void**)&acts, g_acts);
    cudaGetSymbolAddress((void**)&skip, g_skip);
    cudaGetSymbolAddress((void**)&h,    g_h);
    cudaGetSymbolAddress((void**)&iWd,  g_imgWd);
    cudaGetSymbolAddress((void**)&iWr,  g_imgWr);
    cudaGetSymbolAddress((void**)&iWs,  g_imgWs);
    cudaGetSymbolAddress((void**)&iP1,  g_imgP1);
    cudaGetSymbolAddress((void**)&iP2,  g_imgP2);

    // one-time weight images (tf32 + fragment permutation + swizzle)
    prep64<<<5120, 256>>>(Wd, 5120, 256, iWd);
    prep32<<<1280, 256>>>(Wr, 2560, iWr);
    prep64<<<5120, 256>>>(Ws, 2560, 512, iWs);
    prep64<<<1024, 256>>>(p1, 512, 512, iP1);
    prep64<<<512,  256>>>(p2, 512, 256, iP2);

    embed_kernel<<<dim3(TFULL / 32, 8), 256>>>(y, emb, x0);

    float* xin = x0;
    float* xout = x1;
    int Tin = TFULL;
    for (int i = 0; i < NL; ++i) {
        int d = dil[i];
        int Lout = Tin - d;
        dim3 grid((Lout + 127) / 128, 8);
        layer_kernel<<<grid, 512, smemL>>>(
            xin, xout,
            iWd, bd + (size_t)i * 2 * WD,
            iWr, br + (size_t)i * WD,
            d, Lout, i);
        float* tmp = xin; xin = xout; xout = tmp;
        Tin = Lout;
    }

    dim3 g1((FOP + 127) / 128, 2, 8);
    gemm_mma<<<g1, 512, smemG>>>(acts, iWs, bs, NL, 1, NL * WD, 512, skip, FOP, FOP);
    gemm_mma<<<g1, 512, smemG>>>(skip, iP1, nullptr, 0, 1, 512, 512, h, FOP, FOP);
    dim3 g3((FOP + 127) / 128, 1, 8);
    gemm_mma<<<g3, 512, smemG>>>(h, iP2, nullptr, 0, 0, 512, 256, out, FO, FO);
}

// round 11
// speedup vs baseline: 3.1715x; 1.2127x over previous
#include <cuda_runtime.h>
#include <cuda_fp16.h>
#include <math.h>

#define WD 128
#define FO 6145
#define TP 6400           // t-major padded rows
#define TFULL 8192
#define NL 20

// ---------------- scratch ----------------------------------------------------
__device__ __align__(256) float g_x0[(size_t)8 * WD * TFULL + 2048];
__device__ __align__(256) float g_x1[(size_t)8 * WD * TFULL + 2048];
__device__ __align__(256) unsigned short g_actsH[(size_t)8 * TP * 2560]; // [b][t][l*128+c]
__device__ __align__(256) unsigned short g_skipH[(size_t)8 * TP * 512];  // [b][t][o]
__device__ __align__(256) unsigned short g_hH[(size_t)8 * TP * 512];
__device__ __align__(256) unsigned g_iWd[(size_t)NL * 32768];  // fragment-packed half2
__device__ __align__(256) unsigned g_iWr[(size_t)NL * 8192];
__device__ __align__(256) unsigned g_iWs[655360];
__device__ __align__(256) unsigned g_iP1[131072];
__device__ __align__(256) unsigned g_iP2[65536];

// ---------------- helpers ----------------------------------------------------
__device__ __forceinline__ void mmaf16(float* c, uint4 a, uint2 b) {
    asm volatile("mma.sync.aligned.m16n8k16.row.col.f32.f16.f16.f32 "
                 "{%0,%1,%2,%3},{%4,%5,%6,%7},{%8,%9},{%0,%1,%2,%3};\n"
                 : "+f"(c[0]), "+f"(c[1]), "+f"(c[2]), "+f"(c[3])
                 : "r"(a.x), "r"(a.y), "r"(a.z), "r"(a.w), "r"(b.x), "r"(b.y));
}
__device__ __forceinline__ float tanh_fast(float v) {
    float t; asm("tanh.approx.f32 %0, %1;" : "=f"(t) : "f"(v)); return t;
}
__device__ __forceinline__ void cp16(uint4* dst_smem, const uint4* src) {
    unsigned a = (unsigned)__cvta_generic_to_shared(dst_smem);
    asm volatile("cp.async.cg.shared.global [%0], [%1], 16;" :: "r"(a), "l"(src));
}
#define CP_COMMIT asm volatile("cp.async.commit_group;")
#define CP_WAIT0  asm volatile("cp.async.wait_group 0;")

// B-fragment half index for element (k, t) in a [k-chunks x 128t] tile
__device__ __forceinline__ int bIdx(int k, int t) {
    int ch = k >> 4, kk = k & 15, tt = t >> 3, gg = t & 7;
    int r = kk >> 3, qq = (kk & 7) >> 1, hh = kk & 1;
    return (((ch * 16 + tt) * 32 + gg * 4 + qq) * 2 + r) * 2 + hh;
}
__device__ __forceinline__ void stB(unsigned* Xs, int k, int t, float v) {
    ((__half*)Xs)[bIdx(k, t)] = __float2half_rn(v);
}

// ---------------- weight image prep: fragment-packed fp16 --------------------
// img layout (u32): [ot][chunk(K/16)][mtile(OTB/16)][lane(32)][r(4)]
__global__ void __launch_bounds__(256) prepWA(
    const float* __restrict__ W, int K, int NO, unsigned* __restrict__ img,
    int perLW, int perLI)
{
    const float* Wl = W + (size_t)blockIdx.y * perLW;
    unsigned* il = img + (size_t)blockIdx.y * perLI;
    int OTB = (NO >= 256) ? 256 : NO;
    int mtiles = OTB / 16, chunks = K / 16;
    int total = (K * NO) >> 1;
    for (int idx = blockIdx.x * 256 + threadIdx.x; idx < total; idx += gridDim.x * 256) {
        int r = idx & 3, lane = (idx >> 2) & 31;
        int t2 = idx >> 7;
        int mt = t2 % mtiles; t2 /= mtiles;
        int ch = t2 % chunks; int ot = t2 / chunks;
        int m = ot * OTB + mt * 16 + (lane >> 2) + (r & 1) * 8;
        int k0 = ch * 16 + (lane & 3) * 2 + (r >> 1) * 8;
        __half2 h = __floats2half2_rn(Wl[(size_t)k0 * NO + m], Wl[(size_t)(k0 + 1) * NO + m]);
        il[idx] = *(unsigned*)&h;
    }
}

// ---------------- embedding ---------------------------------------------------
__global__ void __launch_bounds__(256) embed_kernel(
    const int* __restrict__ y, const float* __restrict__ emb, float* __restrict__ x)
{
    int b = blockIdx.y;
    int t = blockIdx.x * 32 + (threadIdx.x & 31);
    int cg = threadIdx.x >> 5;
    int idx = y[b * TFULL + t];
    const float* er = emb + (size_t)idx * WD;
    float* xb = x + (size_t)b * WD * TFULL;
#pragma unroll
    for (int j = 0; j < 16; ++j) xb[(size_t)(cg * 16 + j) * TFULL + t] = er[cg * 16 + j];
}

// ---------------- fused per-layer kernel (fp16 mma) --------------------------
__global__ void __launch_bounds__(512, 1) layer_kernel(
    const float* __restrict__ xin, float* __restrict__ xout,
    const unsigned* __restrict__ iWd, const float* __restrict__ bdl,
    const unsigned* __restrict__ iWr, const float* __restrict__ brl,
    int d, int Lout, int layer)
{
    extern __shared__ unsigned sm[];
    unsigned* Xs = sm;            // 16384 u32: B-fragment tile, 256k x 128t
    unsigned* Wb = sm + 16384;    // 8192 u32: weight ping-pong
    unsigned* Sg = sm + 24576;    // 8192 u32: acts staging [t][c] halfs

    const int tid = threadIdx.x;
    const int w = tid >> 5, lane = tid & 31, g = lane >> 2, q = lane & 3;
    const int b = blockIdx.y;
    const int t0 = blockIdx.x * 128;
    const float* xb = xin + (size_t)b * WD * TFULL;
    const unsigned* iWdl = iWd + (size_t)layer * 32768;
    const unsigned* iWrl = iWr + (size_t)layer * 8192;

    // stage phase1 k32-stage 0
    for (int i = tid; i < 1024; i += 512) cp16((uint4*)Wb + i, (const uint4*)iWdl + i);
    CP_COMMIT;

    // X tile into B-fragment layout (tap0 rows k 0..127, tap1 rows 128..255)
    for (int i = tid; i < 128 * 32; i += 512) {
        int k = i >> 5, t4 = (i & 31) << 2;
        int tg = t0 + t4; if (tg > TFULL - 4) tg = TFULL - 4;
        float4 v = *(const float4*)(xb + (size_t)k * TFULL + tg);
        stB(Xs, k, t4, v.x); stB(Xs, k, t4 + 1, v.y);
        stB(Xs, k, t4 + 2, v.z); stB(Xs, k, t4 + 3, v.w);
    }
    if ((d & 3) == 0) {
        for (int i = tid; i < 128 * 32; i += 512) {
            int k = i >> 5, t4 = (i & 31) << 2;
            int tg = t0 + t4 + d; if (tg > TFULL - 4) tg = TFULL - 4;
            float4 v = *(const float4*)(xb + (size_t)k * TFULL + tg);
            stB(Xs, 128 + k, t4, v.x); stB(Xs, 128 + k, t4 + 1, v.y);
            stB(Xs, 128 + k, t4 + 2, v.z); stB(Xs, 128 + k, t4 + 3, v.w);
        }
    } else {
        for (int i = tid; i < 128 * 128; i += 512) {
            int k = i >> 7, t = i & 127;
            int tg = t0 + t + d; if (tg > TFULL - 1) tg = TFULL - 1;
            stB(Xs, 128 + k, t, xb[(size_t)k * TFULL + tg]);
        }
    }

    const int m0 = (w & 3) * 64, n0 = (w >> 2) * 32;
    const int mtb = (w & 3) * 4, ntb = n0 >> 3;

    float acc[4][4][4];
#pragma unroll
    for (int mf = 0; mf < 4; ++mf)
#pragma unroll
        for (int nf = 0; nf < 4; ++nf)
#pragma unroll
            for (int e = 0; e < 4; ++e) acc[mf][nf][e] = 0.0f;

    // ---- Phase 1: 8 stages of k32
    for (int s = 0; s < 8; ++s) {
        CP_WAIT0;
        __syncthreads();
        if (s < 7) {
            const uint4* src = (const uint4*)(iWdl + (s + 1) * 4096);
            uint4* dst = (uint4*)(Wb + ((s + 1) & 1) * 4096);
            for (int i = tid; i < 1024; i += 512) cp16(dst + i, src + i);
            CP_COMMIT;
        } else {
            if (tid < 512) cp16((uint4*)Wb + tid, (const uint4*)iWrl + tid);
            CP_COMMIT;
        }
        const unsigned* Wst = Wb + (s & 1) * 4096;
#pragma unroll
        for (int sub = 0; sub < 2; ++sub) {
            int chAbs = s * 2 + sub;
            uint4 A[4]; uint2 B[4];
#pragma unroll
            for (int mf = 0; mf < 4; ++mf)
                A[mf] = *(const uint4*)(Wst + ((sub * 16 + mtb + mf) * 32 + lane) * 4);
#pragma unroll
            for (int nf = 0; nf < 4; ++nf)
                B[nf] = *(const uint2*)(Xs + ((chAbs * 16 + ntb + nf) * 32 + lane) * 2);
#pragma unroll
            for (int mf = 0; mf < 4; ++mf)
#pragma unroll
                for (int nf = 0; nf < 4; ++nf)
                    mmaf16(acc[mf][nf], A[mf], B[nf]);
        }
    }
    __syncthreads();   // all reads of Xs done before gate overwrites

    // ---- gate: hi warps write sigmoid (half) into acts slots
    if (m0 >= 128) {
#pragma unroll
        for (int mf = 0; mf < 4; ++mf) {
            int r0 = m0 + mf * 16 + g;
            float b0v = bdl[r0], b1v = bdl[r0 + 8];
#pragma unroll
            for (int nf = 0; nf < 4; ++nf) {
                int c0 = n0 + nf * 8 + q * 2;
#pragma unroll
                for (int e = 0; e < 4; ++e) {
                    int row = r0 + ((e >= 2) ? 8 : 0), col = c0 + (e & 1);
                    float v = acc[mf][nf][e] + ((e >= 2) ? b1v : b0v);
                    stB(Xs, row - 128, col, __fdividef(1.0f, 1.0f + __expf(-v)));
                }
            }
        }
    }
    __syncthreads();
    if (m0 < 128) {
#pragma unroll
        for (int mf = 0; mf < 4; ++mf) {
            int r0 = m0 + mf * 16 + g;
            float b0v = bdl[r0], b1v = bdl[r0 + 8];
#pragma unroll
            for (int nf = 0; nf < 4; ++nf) {
                int c0 = n0 + nf * 8 + q * 2;
#pragma unroll
                for (int e = 0; e < 4; ++e) {
                    int row = r0 + ((e >= 2) ? 8 : 0), col = c0 + (e & 1);
                    float v = acc[mf][nf][e] + ((e >= 2) ? b1v : b0v);
                    int hi = bIdx(row, col);
                    float sv = __half2float(((__half*)Xs)[hi]);
                    float av = tanh_fast(v) * sv;
                    ((__half*)Xs)[hi] = __float2half_rn(av);
                    ((__half*)Sg)[col * 128 + row] = __float2half_rn(av);
                }
            }
        }
    }
    __syncthreads();

    // ---- acts tail to g_actsH [b][t][2560] (vectorized from Sg)
    // FIX R10: 128 t x 16 uint4-segments = 2048 iterations (was 1024 -> half
    // the channels never stored, rel_err 0.44)
    {
        const int tail = Lout - FO;
        if (t0 + 128 > tail) {
            __half* ag = (__half*)g_actsH + (size_t)b * TP * 2560 + layer * 128;
            for (int i = tid; i < 2048; i += 512) {
                int t = i >> 4, seg = i & 15;
                int tg = t0 + t;
                if (tg >= tail && tg < Lout)
                    *(uint4*)(ag + (size_t)(tg - tail) * 2560 + seg * 8) =
                        ((const uint4*)Sg)[t * 16 + seg];
            }
        }
    }

    // ---- Phase 2: res GEMM, 4 stages of k32 (B = acts in Xs chunks 0..7)
    const int mtb2 = (w & 3) * 2;
    float ac2[2][4][4];
#pragma unroll
    for (int mf = 0; mf < 2; ++mf)
#pragma unroll
        for (int nf = 0; nf < 4; ++nf)
#pragma unroll
            for (int e = 0; e < 4; ++e) ac2[mf][nf][e] = 0.0f;

    for (int s2 = 0; s2 < 4; ++s2) {
        CP_WAIT0;
        __syncthreads();
        if (s2 < 3) {
            const uint4* src = (const uint4*)(iWrl + (s2 + 1) * 2048);
            uint4* dst = (uint4*)(Wb + ((s2 + 1) & 1) * 4096);
            if (tid < 512) cp16(dst + tid, src + tid);
            CP_COMMIT;
        }
        const unsigned* Wst = Wb + (s2 & 1) * 4096;
#pragma unroll
        for (int sub = 0; sub < 2; ++sub) {
            int chAbs = s2 * 2 + sub;
            uint4 A[2]; uint2 B[4];
#pragma unroll
            for (int mf = 0; mf < 2; ++mf)
                A[mf] = *(const uint4*)(Wst + ((sub * 8 + mtb2 + mf) * 32 + lane) * 4);
#pragma unroll
            for (int nf = 0; nf < 4; ++nf)
                B[nf] = *(const uint2*)(Xs + ((chAbs * 16 + ntb + nf) * 32 + lane) * 2);
#pragma unroll
            for (int mf = 0; mf < 2; ++mf)
#pragma unroll
                for (int nf = 0; nf < 4; ++nf)
                    mmaf16(ac2[mf][nf], A[mf], B[nf]);
        }
    }
    __syncthreads();   // Xs free now; reuse as f32 Rs

    float* Rs = (float*)Xs;
    const int m0b = (w & 3) * 32;
#pragma unroll
    for (int mf = 0; mf < 2; ++mf) {
        int r0 = m0b + mf * 16 + g;
        float br0 = brl[r0], br1 = brl[r0 + 8];
#pragma unroll
        for (int nf = 0; nf < 4; ++nf) {
            int c0 = n0 + nf * 8 + q * 2;
#pragma unroll
            for (int e = 0; e < 4; ++e) {
                int row = r0 + ((e >= 2) ? 8 : 0), col = c0 + (e & 1);
                Rs[row * 128 + col] = ac2[mf][nf][e] + ((e >= 2) ? br1 : br0);
            }
        }
    }
    __syncthreads();

    float* xo = xout + (size_t)b * WD * TFULL;
    for (int i = tid; i < 128 * 128; i += 512) {
        int cc = i >> 7, t = i & 127, tg = t0 + t;
        if (tg < Lout)
            xo[(size_t)cc * TFULL + tg] = Rs[cc * 128 + t] + xb[(size_t)cc * TFULL + tg + d];
    }
}

// ---------------- fp16 GEMM: out[o,t] = sum_k W[k,o]*X[b,t,k] ---------------
// CTA: 256o x 128t, 512 threads, K chunks of 32, double-buffered A(cp.async)+B
__global__ void __launch_bounds__(512, 1) gemm_f16(
    const unsigned short* __restrict__ XH, const unsigned* __restrict__ imgA,
    const float* __restrict__ bias, int nbias, int doRelu,
    int K, int NO, void* __restrict__ outp, int tmajor)
{
    extern __shared__ unsigned sm[];
    unsigned* As = sm;            // 2 x 4096 u32
    unsigned* Bs = sm + 8192;     // 2 x 2048 u32

    const int tid = threadIdx.x;
    const int w = tid >> 5, lane = tid & 31, g = lane >> 2, q = lane & 3;
    const int b = blockIdx.z, ot = blockIdx.y;
    const int t0 = blockIdx.x * 128;
    const int NC = K >> 5, chunks = K >> 4;
    const __half* Xb = (const __half*)XH + (size_t)b * TP * K;
    const unsigned* imgOt = imgA + (size_t)ot * chunks * 2048;

    const int m0 = (w & 3) * 64, n0 = (w >> 2) * 32;
    const int mtb = (w & 3) * 4, ntb = n0 >> 3;

    // B chunk loader: gmem t-major halfs -> fragment layout
    const int bt = tid >> 2, bj = tid & 3;
    const int bsub = bj >> 1, br_ = bj & 1, btt = bt >> 3, bgg = bt & 7;
    const unsigned bbase = ((bsub * 16 + btt) * 32 + bgg * 4) * 2 + br_;

    {
        for (int i = tid; i < 1024; i += 512) cp16((uint4*)As + i, (const uint4*)imgOt + i);
        CP_COMMIT;
        uint4 v = *(const uint4*)(Xb + (size_t)(t0 + bt) * K + bj * 8);
        Bs[bbase] = v.x; Bs[bbase + 2] = v.y; Bs[bbase + 4] = v.z; Bs[bbase + 6] = v.w;
    }

    float acc[4][4][4];
#pragma unroll
    for (int mf = 0; mf < 4; ++mf)
#pragma unroll
        for (int nf = 0; nf < 4; ++nf)
#pragma unroll
            for (int e = 0; e < 4; ++e) acc[mf][nf][e] = 0.0f;

    for (int c = 0; c < NC; ++c) {
        CP_WAIT0;
        __syncthreads();
        if (c + 1 < NC) {
            const uint4* src = (const uint4*)(imgOt + (c + 1) * 4096);
            uint4* dst = (uint4*)(As + ((c + 1) & 1) * 4096);
            for (int i = tid; i < 1024; i += 512) cp16(dst + i, src + i);
            CP_COMMIT;
            uint4 v = *(const uint4*)(Xb + (size_t)(t0 + bt) * K + (c + 1) * 32 + bj * 8);
            unsigned* Bd = Bs + ((c + 1) & 1) * 2048;
            Bd[bbase] = v.x; Bd[bbase + 2] = v.y; Bd[bbase + 4] = v.z; Bd[bbase + 6] = v.w;
        }
        const unsigned* Wst = As + (c & 1) * 4096;
        const unsigned* Bst = Bs + (c & 1) * 2048;
#pragma unroll
        for (int sub = 0; sub < 2; ++sub) {
            uint4 A[4]; uint2 B[4];
#pragma unroll
            for (int mf = 0; mf < 4; ++mf)
                A[mf] = *(const uint4*)(Wst + ((sub * 16 + mtb + mf) * 32 + lane) * 4);
#pragma unroll
            for (int nf = 0; nf < 4; ++nf)
                B[nf] = *(const uint2*)(Bst + ((sub * 16 + ntb + nf) * 32 + lane) * 2);
#pragma unroll
            for (int mf = 0; mf < 4; ++mf)
#pragma unroll
                for (int nf = 0; nf < 4; ++nf)
                    mmaf16(acc[mf][nf], A[mf], B[nf]);
        }
    }

    // epilogue
#pragma unroll
    for (int mf = 0; mf < 4; ++mf) {
        int r0 = ot * 256 + m0 + mf * 16 + g;
        float bs0 = 0.0f, bs1 = 0.0f;
        for (int i = 0; i < nbias; ++i) {
            bs0 += bias[(size_t)i * NO + r0];
            bs1 += bias[(size_t)i * NO + r0 + 8];
        }
#pragma unroll
        for (int nf = 0; nf < 4; ++nf) {
            int c0 = t0 + n0 + nf * 8 + q * 2;
#pragma unroll
            for (int e = 0; e < 4; ++e) {
                int row = r0 + ((e >= 2) ? 8 : 0);
                int t = c0 + (e & 1);
                float v = acc[mf][nf][e] + ((e >= 2) ? bs1 : bs0);
                if (doRelu) v = fmaxf(v, 0.0f);
                if (tmajor) {
                    ((__half*)outp)[((size_t)b * TP + t) * NO + row] = __float2half_rn(v);
                } else {
                    if (t < FO)
                        ((float*)outp)[((size_t)b * NO + row) * FO + t] = v;
                }
            }
        }
    }
}

// ---------------- host launcher ----------------------------------------------
extern "C" void kernel_launch(void* const* d_in, const int* in_sizes, int n_in,
                              void* d_out, int out_size)
{
    const int*   y   = (const int*)d_in[0];
    const float* emb = (const float*)d_in[1];
    const float* Wd  = (const float*)d_in[2];
    const float* bd  = (const float*)d_in[3];
    const float* Wr  = (const float*)d_in[4];
    const float* br  = (const float*)d_in[5];
    const float* Ws  = (const float*)d_in[6];
    const float* bs  = (const float*)d_in[7];
    const float* p1  = (const float*)d_in[8];
    const float* p2  = (const float*)d_in[9];
    float* out = (float*)d_out;

    static const int dil[NL] = {1, 2, 4, 8, 16, 32, 64, 128, 256, 512,
                                1, 2, 4, 8, 16, 32, 64, 128, 256, 512};

    size_t smemL = (size_t)32768 * 4;   // 131072 B
    size_t smemG = (size_t)12288 * 4;   //  49152 B
    cudaFuncSetAttribute(layer_kernel, cudaFuncAttributeMaxDynamicSharedMemorySize, (int)smemL);
    cudaFuncSetAttribute(gemm_f16,     cudaFuncAttributeMaxDynamicSharedMemorySize, (int)smemG);

    float *x0, *x1;
    unsigned short *actsH, *skipH, *hH;
    unsigned *iWd, *iWr, *iWs, *iP1, *iP2;
    cudaGetSymbolAddress((void**)&x0,    g_x0);
    cudaGetSymbolAddress((void**)&x1,    g_x1);
    cudaGetSymbolAddress((void**)&actsH, g_actsH);
    cudaGetSymbolAddress((void**)&skipH, g_skipH);
    cudaGetSymbolAddress((void**)&hH,    g_hH);
    cudaGetSymbolAddress((void**)&iWd,   g_iWd);
    cudaGetSymbolAddress((void**)&iWr,   g_iWr);
    cudaGetSymbolAddress((void**)&iWs,   g_iWs);
    cudaGetSymbolAddress((void**)&iP1,   g_iP1);
    cudaGetSymbolAddress((void**)&iP2,   g_iP2);

    // fragment-packed fp16 weight images
    prepWA<<<dim3(128, NL), 256>>>(Wd, 256, 256, iWd, 65536, 32768);
    prepWA<<<dim3(32,  NL), 256>>>(Wr, 128, 128, iWr, 16384, 8192);
    prepWA<<<dim3(512, 1),  256>>>(Ws, 2560, 512, iWs, 0, 0);
    prepWA<<<dim3(128, 1),  256>>>(p1, 512, 512, iP1, 0, 0);
    prepWA<<<dim3(64,  1),  256>>>(p2, 512, 256, iP2, 0, 0);

    embed_kernel<<<dim3(TFULL / 32, 8), 256>>>(y, emb, x0);

    float* xin = x0;
    float* xout = x1;
    int Tin = TFULL;
    for (int i = 0; i < NL; ++i) {
        int d = dil[i];
        int Lout = Tin - d;
        dim3 grid((Lout + 127) / 128, 8);
        layer_kernel<<<grid, 512, smemL>>>(
            xin, xout, iWd, bd + (size_t)i * 2 * WD, iWr, br + (size_t)i * WD,
            d, Lout, i);
        float* tmp = xin; xin = xout; xout = tmp;
        Tin = Lout;
    }

    dim3 g1(TP / 128, 2, 8);
    gemm_f16<<<g1, 512, smemG>>>(actsH, iWs, bs, NL, 1, 2560, 512, skipH, 1);
    gemm_f16<<<g1, 512, smemG>>>(skipH, iP1, nullptr, 0, 1, 512, 512, hH, 1);
    dim3 g3(TP / 128, 1, 8);
    gemm_f16<<<g3, 512, smemG>>>(hH, iP2, nullptr, 0, 0, 512, 256, out, 0);
}

// round 13
// speedup vs baseline: 3.3376x; 1.0524x over previous
#include <cuda_runtime.h>
#include <cuda_fp16.h>
#include <math.h>

#define WD 128
#define FO 6145
#define TP 6400           // t-major padded rows
#define TFULL 8192
#define NL 20

// ---------------- scratch ----------------------------------------------------
__device__ __align__(256) float g_x0[(size_t)8 * WD * TFULL + 2048];
__device__ __align__(256) float g_x1[(size_t)8 * WD * TFULL + 2048];
__device__ __align__(256) unsigned short g_actsH[(size_t)8 * TP * 2560]; // [b][t][l*128+c]
__device__ __align__(256) unsigned short g_skipH[(size_t)8 * TP * 512];  // [b][t][o]
__device__ __align__(256) unsigned short g_hH[(size_t)8 * TP * 512];
__device__ __align__(256) unsigned g_iWd[(size_t)NL * 32768];  // fragment-packed half2
__device__ __align__(256) unsigned g_iWr[(size_t)NL * 8192];
__device__ __align__(256) unsigned g_iWs[655360];
__device__ __align__(256) unsigned g_iP1[131072];
__device__ __align__(256) unsigned g_iP2[65536];

// ---------------- helpers ----------------------------------------------------
__device__ __forceinline__ void mmaf16(float* c, uint4 a, uint2 b) {
    asm volatile("mma.sync.aligned.m16n8k16.row.col.f32.f16.f16.f32 "
                 "{%0,%1,%2,%3},{%4,%5,%6,%7},{%8,%9},{%0,%1,%2,%3};\n"
                 : "+f"(c[0]), "+f"(c[1]), "+f"(c[2]), "+f"(c[3])
                 : "r"(a.x), "r"(a.y), "r"(a.z), "r"(a.w), "r"(b.x), "r"(b.y));
}
__device__ __forceinline__ float tanh_fast(float v) {
    float t; asm("tanh.approx.f32 %0, %1;" : "=f"(t) : "f"(v)); return t;
}
__device__ __forceinline__ void cp16(uint4* dst_smem, const uint4* src) {
    unsigned a = (unsigned)__cvta_generic_to_shared(dst_smem);
    asm volatile("cp.async.cg.shared.global [%0], [%1], 16;" :: "r"(a), "l"(src));
}
#define CP_COMMIT asm volatile("cp.async.commit_group;")
#define CP_WAIT0  asm volatile("cp.async.wait_group 0;")
#define CP_WAIT1  asm volatile("cp.async.wait_group 1;")

// B-fragment half index for element (k, t) in a [k-chunks x 128t] tile
__device__ __forceinline__ int bIdx(int k, int t) {
    int ch = k >> 4, kk = k & 15, tt = t >> 3, gg = t & 7;
    int r = kk >> 3, qq = (kk & 7) >> 1, hh = kk & 1;
    return (((ch * 16 + tt) * 32 + gg * 4 + qq) * 2 + r) * 2 + hh;
}
__device__ __forceinline__ void stB(unsigned* Xs, int k, int t, float v) {
    ((__half*)Xs)[bIdx(k, t)] = __float2half_rn(v);
}

// ---------------- weight image prep: fragment-packed fp16 --------------------
// img layout (u32): [ot][chunk(K/16)][mtile(OTB/16)][lane(32)][r(4)]
__global__ void __launch_bounds__(256) prepWA(
    const float* __restrict__ W, int K, int NO, unsigned* __restrict__ img,
    int perLW, int perLI)
{
    const float* Wl = W + (size_t)blockIdx.y * perLW;
    unsigned* il = img + (size_t)blockIdx.y * perLI;
    int OTB = (NO >= 256) ? 256 : NO;
    int mtiles = OTB / 16, chunks = K / 16;
    int total = (K * NO) >> 1;
    for (int idx = blockIdx.x * 256 + threadIdx.x; idx < total; idx += gridDim.x * 256) {
        int r = idx & 3, lane = (idx >> 2) & 31;
        int t2 = idx >> 7;
        int mt = t2 % mtiles; t2 /= mtiles;
        int ch = t2 % chunks; int ot = t2 / chunks;
        int m = ot * OTB + mt * 16 + (lane >> 2) + (r & 1) * 8;
        int k0 = ch * 16 + (lane & 3) * 2 + (r >> 1) * 8;
        __half2 h = __floats2half2_rn(Wl[(size_t)k0 * NO + m], Wl[(size_t)(k0 + 1) * NO + m]);
        il[idx] = *(unsigned*)&h;
    }
}

// ---------------- embedding ---------------------------------------------------
__global__ void __launch_bounds__(256) embed_kernel(
    const int* __restrict__ y, const float* __restrict__ emb, float* __restrict__ x)
{
    int b = blockIdx.y;
    int t = blockIdx.x * 32 + (threadIdx.x & 31);
    int cg = threadIdx.x >> 5;
    int idx = y[b * TFULL + t];
    const float* er = emb + (size_t)idx * WD;
    float* xb = x + (size_t)b * WD * TFULL;
#pragma unroll
    for (int j = 0; j < 16; ++j) xb[(size_t)(cg * 16 + j) * TFULL + t] = er[cg * 16 + j];
}

// ---------------- fused per-layer kernel (fp16 mma, 3-deep weight ring) ------
__global__ void __launch_bounds__(512, 1) layer_kernel(
    const float* __restrict__ xin, float* __restrict__ xout,
    const unsigned* __restrict__ iWd, const float* __restrict__ bdl,
    const unsigned* __restrict__ iWr, const float* __restrict__ brl,
    int d, int Lout, int layer)
{
    extern __shared__ unsigned sm[];
    unsigned* Xs = sm;            // 16384 u32: B-fragment tile, 256k x 128t
    unsigned* Wr3 = sm + 16384;   // 3 x 4096 u32: weight ring
    unsigned* Sg = sm + 28672;    // 8192 u32: acts staging [t][c] halfs

    const int tid = threadIdx.x;
    const int w = tid >> 5, lane = tid & 31, g = lane >> 2, q = lane & 3;
    const int b = blockIdx.y;
    const int t0 = blockIdx.x * 128;
    const float* xb = xin + (size_t)b * WD * TFULL;
    const unsigned* iWdl = iWd + (size_t)layer * 32768;
    const unsigned* iWrl = iWr + (size_t)layer * 8192;

    // stage content u: u<8 -> Wd chunk u (4096 u32); u>=8 -> Wr chunk u-8 (2048 u32)
    auto issueW = [&](int u) {
        uint4* dst = (uint4*)(Wr3 + (u % 3) * 4096);
        if (u < 8) {
            const uint4* src = (const uint4*)(iWdl + u * 4096);
            for (int i = tid; i < 1024; i += 512) cp16(dst + i, src + i);
        } else {
            const uint4* src = (const uint4*)(iWrl + (u - 8) * 2048);
            cp16(dst + tid, src + tid);
        }
        CP_COMMIT;
    };

    issueW(0);
    issueW(1);

    // X tile into B-fragment layout (tap0 rows k 0..127, tap1 rows 128..255)
    for (int i = tid; i < 128 * 32; i += 512) {
        int k = i >> 5, t4 = (i & 31) << 2;
        int tg = t0 + t4; if (tg > TFULL - 4) tg = TFULL - 4;
        float4 v = *(const float4*)(xb + (size_t)k * TFULL + tg);
        stB(Xs, k, t4, v.x); stB(Xs, k, t4 + 1, v.y);
        stB(Xs, k, t4 + 2, v.z); stB(Xs, k, t4 + 3, v.w);
    }
    if ((d & 3) == 0) {
        for (int i = tid; i < 128 * 32; i += 512) {
            int k = i >> 5, t4 = (i & 31) << 2;
            int tg = t0 + t4 + d; if (tg > TFULL - 4) tg = TFULL - 4;
            float4 v = *(const float4*)(xb + (size_t)k * TFULL + tg);
            stB(Xs, 128 + k, t4, v.x); stB(Xs, 128 + k, t4 + 1, v.y);
            stB(Xs, 128 + k, t4 + 2, v.z); stB(Xs, 128 + k, t4 + 3, v.w);
        }
    } else {
        for (int i = tid; i < 128 * 128; i += 512) {
            int k = i >> 7, t = i & 127;
            int tg = t0 + t + d; if (tg > TFULL - 1) tg = TFULL - 1;
            stB(Xs, 128 + k, t, xb[(size_t)k * TFULL + tg]);
        }
    }

    const int m0 = (w & 3) * 64, n0 = (w >> 2) * 32;
    const int mtb = (w & 3) * 4, ntb = n0 >> 3;

    float acc[4][4][4];
#pragma unroll
    for (int mf = 0; mf < 4; ++mf)
#pragma unroll
        for (int nf = 0; nf < 4; ++nf)
#pragma unroll
            for (int e = 0; e < 4; ++e) acc[mf][nf][e] = 0.0f;

    // ---- Phase 1: stages u = 0..7 (k32 each), 2-deep prefetch
    for (int u = 0; u < 8; ++u) {
        CP_WAIT1;
        __syncthreads();
        issueW(u + 2);                        // u+2 <= 9 < 12 always
        const unsigned* Wst = Wr3 + (u % 3) * 4096;
#pragma unroll
        for (int sub = 0; sub < 2; ++sub) {
            int chAbs = u * 2 + sub;
            uint4 A[4]; uint2 B[4];
#pragma unroll
            for (int mf = 0; mf < 4; ++mf)
                A[mf] = *(const uint4*)(Wst + ((sub * 16 + mtb + mf) * 32 + lane) * 4);
#pragma unroll
            for (int nf = 0; nf < 4; ++nf)
                B[nf] = *(const uint2*)(Xs + ((chAbs * 16 + ntb + nf) * 32 + lane) * 2);
#pragma unroll
            for (int mf = 0; mf < 4; ++mf)
#pragma unroll
                for (int nf = 0; nf < 4; ++nf)
                    mmaf16(acc[mf][nf], A[mf], B[nf]);
        }
    }
    __syncthreads();   // all reads of Xs done before gate overwrites

    // ---- gate: hi warps write sigmoid (half) into acts slots
    if (m0 >= 128) {
#pragma unroll
        for (int mf = 0; mf < 4; ++mf) {
            int r0 = m0 + mf * 16 + g;
            float b0v = bdl[r0], b1v = bdl[r0 + 8];
#pragma unroll
            for (int nf = 0; nf < 4; ++nf) {
                int c0 = n0 + nf * 8 + q * 2;
#pragma unroll
                for (int e = 0; e < 4; ++e) {
                    int row = r0 + ((e >= 2) ? 8 : 0), col = c0 + (e & 1);
                    float v = acc[mf][nf][e] + ((e >= 2) ? b1v : b0v);
                    stB(Xs, row - 128, col, __fdividef(1.0f, 1.0f + __expf(-v)));
                }
            }
        }
    }
    __syncthreads();
    if (m0 < 128) {
#pragma unroll
        for (int mf = 0; mf < 4; ++mf) {
            int r0 = m0 + mf * 16 + g;
            float b0v = bdl[r0], b1v = bdl[r0 + 8];
#pragma unroll
            for (int nf = 0; nf < 4; ++nf) {
                int c0 = n0 + nf * 8 + q * 2;
#pragma unroll
                for (int e = 0; e < 4; ++e) {
                    int row = r0 + ((e >= 2) ? 8 : 0), col = c0 + (e & 1);
                    float v = acc[mf][nf][e] + ((e >= 2) ? b1v : b0v);
                    int hi = bIdx(row, col);
                    float sv = __half2float(((__half*)Xs)[hi]);
                    float av = tanh_fast(v) * sv;
                    ((__half*)Xs)[hi] = __float2half_rn(av);
                    ((__half*)Sg)[col * 128 + row] = __float2half_rn(av);
                }
            }
        }
    }
    __syncthreads();

    // ---- acts tail to g_actsH [b][t][2560] (vectorized from Sg)
    {
        const int tail = Lout - FO;
        if (t0 + 128 > tail) {
            __half* ag = (__half*)g_actsH + (size_t)b * TP * 2560 + layer * 128;
            for (int i = tid; i < 2048; i += 512) {
                int t = i >> 4, seg = i & 15;
                int tg = t0 + t;
                if (tg >= tail && tg < Lout)
                    *(uint4*)(ag + (size_t)(tg - tail) * 2560 + seg * 8) =
                        ((const uint4*)Sg)[t * 16 + seg];
            }
        }
    }

    // ---- Phase 2: stages u = 8..11 (k32 each), same ring
    const int mtb2 = (w & 3) * 2;
    float ac2[2][4][4];
#pragma unroll
    for (int mf = 0; mf < 2; ++mf)
#pragma unroll
        for (int nf = 0; nf < 4; ++nf)
#pragma unroll
            for (int e = 0; e < 4; ++e) ac2[mf][nf][e] = 0.0f;

    for (int u = 8; u < 12; ++u) {
        if (u < 11) { CP_WAIT1; } else { CP_WAIT0; }
        __syncthreads();
        if (u + 2 < 12) issueW(u + 2);
        const unsigned* Wst = Wr3 + (u % 3) * 4096;
        int s2 = u - 8;
#pragma unroll
        for (int sub = 0; sub < 2; ++sub) {
            int chAbs = s2 * 2 + sub;
            uint4 A[2]; uint2 B[4];
#pragma unroll
            for (int mf = 0; mf < 2; ++mf)
                A[mf] = *(const uint4*)(Wst + ((sub * 8 + mtb2 + mf) * 32 + lane) * 4);
#pragma unroll
            for (int nf = 0; nf < 4; ++nf)
                B[nf] = *(const uint2*)(Xs + ((chAbs * 16 + ntb + nf) * 32 + lane) * 2);
#pragma unroll
            for (int mf = 0; mf < 2; ++mf)
#pragma unroll
                for (int nf = 0; nf < 4; ++nf)
                    mmaf16(ac2[mf][nf], A[mf], B[nf]);
        }
    }
    __syncthreads();   // Xs free now; reuse as f32 Rs

    float* Rs = (float*)Xs;
    const int m0b = (w & 3) * 32;
#pragma unroll
    for (int mf = 0; mf < 2; ++mf) {
        int r0 = m0b + mf * 16 + g;
        float br0 = brl[r0], br1 = brl[r0 + 8];
#pragma unroll
        for (int nf = 0; nf < 4; ++nf) {
            int c0 = n0 + nf * 8 + q * 2;
#pragma unroll
            for (int e = 0; e < 4; ++e) {
                int row = r0 + ((e >= 2) ? 8 : 0), col = c0 + (e & 1);
                Rs[row * 128 + col] = ac2[mf][nf][e] + ((e >= 2) ? br1 : br0);
            }
        }
    }
    __syncthreads();

    float* xo = xout + (size_t)b * WD * TFULL;
    for (int i = tid; i < 128 * 128; i += 512) {
        int cc = i >> 7, t = i & 127, tg = t0 + t;
        if (tg < Lout)
            xo[(size_t)cc * TFULL + tg] = Rs[cc * 128 + t] + xb[(size_t)cc * TFULL + tg + d];
    }
}

// ---------------- fp16 GEMM: out[o,t] = sum_k W[k,o]*X[b,t,k] ---------------
// CTA: 256o x 128t, 512 threads, K chunks of 32, 3-deep A/B rings,
// B LDG hoisted above compute, STS after compute.
__global__ void __launch_bounds__(512, 1) gemm_f16(
    const unsigned short* __restrict__ XH, const unsigned* __restrict__ imgA,
    const float* __restrict__ bias, int nbias, int doRelu,
    int K, int NO, void* __restrict__ outp, int tmajor)
{
    extern __shared__ unsigned sm[];
    unsigned* As3 = sm;            // 3 x 4096 u32
    unsigned* Bs3 = sm + 12288;    // 3 x 2048 u32

    const int tid = threadIdx.x;
    const int w = tid >> 5, lane = tid & 31, g = lane >> 2, q = lane & 3;
    const int b = blockIdx.z, ot = blockIdx.y;
    const int t0 = blockIdx.x * 128;
    const int NC = K >> 5, chunks = K >> 4;
    const __half* Xb = (const __half*)XH + (size_t)b * TP * K;
    const unsigned* imgOt = imgA + (size_t)ot * chunks * 2048;

    const int m0 = (w & 3) * 64, n0 = (w >> 2) * 32;
    const int mtb = (w & 3) * 4, ntb = n0 >> 3;

    // B chunk loader: gmem t-major halfs -> fragment layout
    const int bt = tid >> 2, bj = tid & 3;
    const int bsub = bj >> 1, br_ = bj & 1, btt = bt >> 3, bgg = bt & 7;
    const unsigned bbase = ((bsub * 16 + btt) * 32 + bgg * 4) * 2 + br_;

    auto issueA = [&](int c) {
        const uint4* src = (const uint4*)(imgOt + c * 4096);
        uint4* dst = (uint4*)(As3 + (c % 3) * 4096);
        for (int i = tid; i < 1024; i += 512) cp16(dst + i, src + i);
        CP_COMMIT;
    };
    auto ldB = [&](int c) {
        return *(const uint4*)(Xb + (size_t)(t0 + bt) * K + c * 32 + bj * 8);
    };
    auto stBreg = [&](int c, uint4 v) {
        unsigned* Bd = Bs3 + (c % 3) * 2048;
        Bd[bbase] = v.x; Bd[bbase + 2] = v.y; Bd[bbase + 4] = v.z; Bd[bbase + 6] = v.w;
    };

    issueA(0); stBreg(0, ldB(0));
    issueA(1); stBreg(1, ldB(1));

    float acc[4][4][4];
#pragma unroll
    for (int mf = 0; mf < 4; ++mf)
#pragma unroll
        for (int nf = 0; nf < 4; ++nf)
#pragma unroll
            for (int e = 0; e < 4; ++e) acc[mf][nf][e] = 0.0f;

    for (int c = 0; c < NC; ++c) {
        if (c + 1 < NC) { CP_WAIT1; } else { CP_WAIT0; }
        __syncthreads();
        uint4 vb;
        const bool pend = (c + 2 < NC);
        if (pend) { issueA(c + 2); vb = ldB(c + 2); }
        const unsigned* Wst = As3 + (c % 3) * 4096;
        const unsigned* Bst = Bs3 + (c % 3) * 2048;
#pragma unroll
        for (int sub = 0; sub < 2; ++sub) {
            uint4 A[4]; uint2 B[4];
#pragma unroll
            for (int mf = 0; mf < 4; ++mf)
                A[mf] = *(const uint4*)(Wst + ((sub * 16 + mtb + mf) * 32 + lane) * 4);
#pragma unroll
            for (int nf = 0; nf < 4; ++nf)
                B[nf] = *(const uint2*)(Bst + ((sub * 16 + ntb + nf) * 32 + lane) * 2);
#pragma unroll
            for (int mf = 0; mf < 4; ++mf)
#pragma unroll
                for (int nf = 0; nf < 4; ++nf)
                    mmaf16(acc[mf][nf], A[mf], B[nf]);
        }
        if (pend) stBreg(c + 2, vb);
    }

    // epilogue
#pragma unroll
    for (int mf = 0; mf < 4; ++mf) {
        int r0 = ot * 256 + m0 + mf * 16 + g;
        float bs0 = 0.0f, bs1 = 0.0f;
        for (int i = 0; i < nbias; ++i) {
            bs0 += bias[(size_t)i * NO + r0];
            bs1 += bias[(size_t)i * NO + r0 + 8];
        }
#pragma unroll
        for (int nf = 0; nf < 4; ++nf) {
            int c0 = t0 + n0 + nf * 8 + q * 2;
#pragma unroll
            for (int e = 0; e < 4; ++e) {
                int row = r0 + ((e >= 2) ? 8 : 0);
                int t = c0 + (e & 1);
                float v = acc[mf][nf][e] + ((e >= 2) ? bs1 : bs0);
                if (doRelu) v = fmaxf(v, 0.0f);
                if (tmajor) {
                    ((__half*)outp)[((size_t)b * TP + t) * NO + row] = __float2half_rn(v);
                } else {
                    if (t < FO)
                        ((float*)outp)[((size_t)b * NO + row) * FO + t] = v;
                }
            }
        }
    }
}

// ---------------- host launcher ----------------------------------------------
extern "C" void kernel_launch(void* const* d_in, const int* in_sizes, int n_in,
                              void* d_out, int out_size)
{
    const int*   y   = (const int*)d_in[0];
    const float* emb = (const float*)d_in[1];
    const float* Wd  = (const float*)d_in[2];
    const float* bd  = (const float*)d_in[3];
    const float* Wr  = (const float*)d_in[4];
    const float* br  = (const float*)d_in[5];
    const float* Ws  = (const float*)d_in[6];
    const float* bs  = (const float*)d_in[7];
    const float* p1  = (const float*)d_in[8];
    const float* p2  = (const float*)d_in[9];
    float* out = (float*)d_out;

    static const int dil[NL] = {1, 2, 4, 8, 16, 32, 64, 128, 256, 512,
                                1, 2, 4, 8, 16, 32, 64, 128, 256, 512};

    size_t smemL = (size_t)(16384 + 12288 + 8192) * 4;   // 147456 B
    size_t smemG = (size_t)(12288 + 6144) * 4;           //  73728 B
    cudaFuncSetAttribute(layer_kernel, cudaFuncAttributeMaxDynamicSharedMemorySize, (int)smemL);
    cudaFuncSetAttribute(gemm_f16,     cudaFuncAttributeMaxDynamicSharedMemorySize, (int)smemG);

    float *x0, *x1;
    unsigned short *actsH, *skipH, *hH;
    unsigned *iWd, *iWr, *iWs, *iP1, *iP2;
    cudaGetSymbolAddress((void**)&x0,    g_x0);
    cudaGetSymbolAddress((void**)&x1,    g_x1);
    cudaGetSymbolAddress((void**)&actsH, g_actsH);
    cudaGetSymbolAddress((void**)&skipH, g_skipH);
    cudaGetSymbolAddress((void**)&hH,    g_hH);
    cudaGetSymbolAddress((void**)&iWd,   g_iWd);
    cudaGetSymbolAddress((void**)&iWr,   g_iWr);
    cudaGetSymbolAddress((void**)&iWs,   g_iWs);
    cudaGetSymbolAddress((void**)&iP1,   g_iP1);
    cudaGetSymbolAddress((void**)&iP2,   g_iP2);

    // fragment-packed fp16 weight images
    prepWA<<<dim3(128, NL), 256>>>(Wd, 256, 256, iWd, 65536, 32768);
    prepWA<<<dim3(32,  NL), 256>>>(Wr, 128, 128, iWr, 16384, 8192);
    prepWA<<<dim3(512, 1),  256>>>(Ws, 2560, 512, iWs, 0, 0);
    prepWA<<<dim3(128, 1),  256>>>(p1, 512, 512, iP1, 0, 0);
    prepWA<<<dim3(64,  1),  256>>>(p2, 512, 256, iP2, 0, 0);

    embed_kernel<<<dim3(TFULL / 32, 8), 256>>>(y, emb, x0);

    float* xin = x0;
    float* xout = x1;
    int Tin = TFULL;
    for (int i = 0; i < NL; ++i) {
        int d = dil[i];
        int Lout = Tin - d;
        dim3 grid((Lout + 127) / 128, 8);
        layer_kernel<<<grid, 512, smemL>>>(
            xin, xout, iWd, bd + (size_t)i * 2 * WD, iWr, br + (size_t)i * WD,
            d, Lout, i);
        float* tmp = xin; xin = xout; xout = tmp;
        Tin = Lout;
    }

    dim3 g1(TP / 128, 2, 8);
    gemm_f16<<<g1, 512, smemG>>>(actsH, iWs, bs, NL, 1, 2560, 512, skipH, 1);
    gemm_f16<<<g1, 512, smemG>>>(skipH, iP1, nullptr, 0, 1, 512, 512, hH, 1);
    dim3 g3(TP / 128, 1, 8);
    gemm_f16<<<g3, 512, smemG>>>(hH, iP2, nullptr, 0, 0, 512, 256, out, 0);
}